// round 1
// baseline (speedup 1.0000x reference)
#include <cuda_runtime.h>
#include <math.h>

// Problem constants
#define BB    4
#define TT    1000000
#define EE    8
#define CC    128
#define KW    512
#define TOUT  1953                 // (1e6 - 512)/512 + 1
#define MROWS (BB * TOUT)          // 7812
#define NCOLS 512                  // 2 branches * 2C? No: ctx 256 + main 256
#define KDIM  4096                 // E * KW

#define NCHUNK 31
#define CHUNK  63                  // 31*63 = 1953

// ---- scratch (static __device__, no allocation) ----
__device__ float d_Wmat[KDIM * NCOLS];      // 8 MB  (kk-major, [kk][n])
__device__ float d_WsT[2][CC * CC];         // share weights transposed [c][o]
__device__ float d_Y[MROWS * NCOLS];        // 16 MB conv outputs (pre-bias)
__device__ float d_g[MROWS * CC];           // ctx branch activations
__device__ float d_h[MROWS * CC];           // main branch activations
__device__ float d_gct[BB * CC];
__device__ float d_q[BB * CC];
__device__ float d_part[BB * NCHUNK * CC];

// ============================================================
// K0a: build Wmat[kk][n]  (kk = k*8 + e), n<256 ctx, n>=256 main
// ============================================================
__global__ void prep_wmat(const float* __restrict__ cw, const float* __restrict__ mw) {
    int idx = blockIdx.x * 256 + threadIdx.x;
    if (idx >= KDIM * NCOLS) return;
    int n  = idx % NCOLS;
    int kk = idx / NCOLS;
    int e = kk & 7;
    int k = kk >> 3;
    float v;
    if (n < 256) v = cw[n * KDIM + e * KW + k];
    else         v = mw[(n - 256) * KDIM + e * KW + k];
    d_Wmat[(size_t)kk * NCOLS + n] = v;
}

// K0b: transpose the two 1x1 share weights: WsT[c][o] = Ws[o][c]
__global__ void prep_wst(const float* __restrict__ cs, const float* __restrict__ ms) {
    int idx = blockIdx.x * 256 + threadIdx.x;
    if (idx >= CC * CC) return;
    int o = idx / CC, c = idx % CC;
    d_WsT[0][c * CC + o] = cs[o * CC + c];
    d_WsT[1][c * CC + o] = ms[o * CC + c];
}

// ============================================================
// K1: SGEMM  Y[7812,512] = A[7812,4096] * Wmat[4096,512]
//     A row r = contiguous window of x (non-overlapping stride==K).
//     BM=64 BN=128 BK=16, 256 threads, 4x8 micro-tile, double-buffered smem.
// ============================================================
#define BM 64
#define BN 128
#define BK 16
#define ASTRIDE 68   // padded, multiple of 4 for float4 smem reads

__global__ __launch_bounds__(256) void gemm_conv(const float* __restrict__ x) {
    __shared__ __align__(16) float As[2][BK * ASTRIDE];
    __shared__ __align__(16) float Bs[2][BK * BN];

    int tid = threadIdx.x;
    int bm = blockIdx.y, bn = blockIdx.x;

    // A-load mapping: one float4 per thread: row am (0..63), k offset ak
    int am = tid >> 2;
    int ak = (tid & 3) * 4;
    int gr = bm * BM + am;
    const float* aptr;
    if (gr < MROWS) {
        int b = gr / TOUT, t = gr % TOUT;
        aptr = x + (size_t)b * TT * EE + (size_t)t * KDIM;
    } else {
        aptr = x;  // harmless garbage; stores guarded
    }

    // B-load mapping: two float4 per thread
    int brow = tid >> 5;          // 0..7 -> rows brow, brow+8
    int bc   = (tid & 31) * 4;    // 0..124
    const float* bbase = d_Wmat + (size_t)bn * BN + bc;

    int tx = tid & 15;            // col group: 8 cols
    int ty = tid >> 4;            // row group: 4 rows

    float acc[4][8];
#pragma unroll
    for (int i = 0; i < 4; i++)
#pragma unroll
        for (int j = 0; j < 8; j++) acc[i][j] = 0.f;

    // prologue: tile 0
    float4 ra = *(const float4*)(aptr + ak);
    float4 rb0 = *(const float4*)(bbase + (size_t)brow * NCOLS);
    float4 rb1 = *(const float4*)(bbase + (size_t)(brow + 8) * NCOLS);

    As[0][(ak + 0) * ASTRIDE + am] = ra.x;
    As[0][(ak + 1) * ASTRIDE + am] = ra.y;
    As[0][(ak + 2) * ASTRIDE + am] = ra.z;
    As[0][(ak + 3) * ASTRIDE + am] = ra.w;
    *(float4*)(&Bs[0][brow * BN + bc])       = rb0;
    *(float4*)(&Bs[0][(brow + 8) * BN + bc]) = rb1;
    __syncthreads();

    const int NK = KDIM / BK;  // 256
    for (int kt = 0; kt < NK; kt++) {
        int cur = kt & 1;
        if (kt + 1 < NK) {
            int k0 = (kt + 1) * BK;
            ra  = *(const float4*)(aptr + k0 + ak);
            rb0 = *(const float4*)(bbase + (size_t)(k0 + brow) * NCOLS);
            rb1 = *(const float4*)(bbase + (size_t)(k0 + brow + 8) * NCOLS);
        }
        const float* Ac = As[cur];
        const float* Bc = Bs[cur];
#pragma unroll
        for (int k = 0; k < BK; k++) {
            float4 av = *(const float4*)(Ac + k * ASTRIDE + ty * 4);
            float4 b0 = *(const float4*)(Bc + k * BN + tx * 8);
            float4 b1 = *(const float4*)(Bc + k * BN + tx * 8 + 4);
            float a_[4] = {av.x, av.y, av.z, av.w};
            float b_[8] = {b0.x, b0.y, b0.z, b0.w, b1.x, b1.y, b1.z, b1.w};
#pragma unroll
            for (int i = 0; i < 4; i++)
#pragma unroll
                for (int j = 0; j < 8; j++)
                    acc[i][j] += a_[i] * b_[j];
        }
        if (kt + 1 < NK) {
            int nxt = cur ^ 1;
            As[nxt][(ak + 0) * ASTRIDE + am] = ra.x;
            As[nxt][(ak + 1) * ASTRIDE + am] = ra.y;
            As[nxt][(ak + 2) * ASTRIDE + am] = ra.z;
            As[nxt][(ak + 3) * ASTRIDE + am] = ra.w;
            *(float4*)(&Bs[nxt][brow * BN + bc])       = rb0;
            *(float4*)(&Bs[nxt][(brow + 8) * BN + bc]) = rb1;
            __syncthreads();
        }
    }

    // epilogue
#pragma unroll
    for (int i = 0; i < 4; i++) {
        int row = bm * BM + ty * 4 + i;
        if (row < MROWS) {
            float* yp = d_Y + (size_t)row * NCOLS + bn * BN + tx * 8;
            float4 w0 = make_float4(acc[i][0], acc[i][1], acc[i][2], acc[i][3]);
            float4 w1 = make_float4(acc[i][4], acc[i][5], acc[i][6], acc[i][7]);
            *(float4*)(yp)     = w0;
            *(float4*)(yp + 4) = w1;
        }
    }
}

// ============================================================
// K2: per-row: bias + GLU -> u (128 per branch), then 1x1 share
//     conv (128x128) + bias + leaky, write d_g / d_h.
//     Block = 32 rows; thread o in [0,256): branch = o>>7.
// ============================================================
#define R2 32
__global__ __launch_bounds__(256) void glu_share(const float* __restrict__ cb,
                                                 const float* __restrict__ csb,
                                                 const float* __restrict__ mb,
                                                 const float* __restrict__ msb) {
    __shared__ float u[R2][256];
    int tid = threadIdx.x;
    int row0 = blockIdx.x * R2;

    for (int idx = tid; idx < R2 * 256; idx += 256) {
        int r = idx >> 8;
        int j = idx & 255;
        int row = row0 + r;
        float val = 0.f;
        if (row < MROWS) {
            const float* yrow = d_Y + (size_t)row * NCOLS;
            int half = j & 127;
            float a, bg;
            if (j < 128) {
                a  = yrow[half]       + cb[half];
                bg = yrow[half + 128] + cb[half + 128];
            } else {
                a  = yrow[half + 256] + mb[half];
                bg = yrow[half + 384] + mb[half + 128];
            }
            val = a / (1.f + expf(-bg));   // a * sigmoid(bg)
        }
        u[r][j] = val;
    }
    __syncthreads();

    int branch = tid >> 7;     // 0 = ctx, 1 = main
    int oc = tid & 127;
    const float* wt = d_WsT[branch];
    int uoff = branch * 128;

    float acc[R2];
#pragma unroll
    for (int r = 0; r < R2; r++) acc[r] = 0.f;

    for (int c = 0; c < CC; c++) {
        float wv = __ldg(&wt[c * CC + oc]);
#pragma unroll
        for (int r = 0; r < R2; r++) acc[r] += wv * u[r][uoff + c];
    }

    float bias = branch ? msb[oc] : csb[oc];
    float* dst = branch ? d_h : d_g;
#pragma unroll
    for (int r = 0; r < R2; r++) {
        int row = row0 + r;
        if (row < MROWS) {
            float v = acc[r] + bias;
            v = (v >= 0.f) ? v : 0.01f * v;
            dst[(size_t)row * CC + oc] = v;
        }
    }
}

// K3: gct[b][c] = max_t g[b,c,t]
__global__ void reduce_gct() {
    int b = blockIdx.x;
    int c = threadIdx.x;
    float m = -INFINITY;
    const float* gp = d_g + (size_t)b * TOUT * CC + c;
    for (int t = 0; t < TOUT; t++) m = fmaxf(m, gp[(size_t)t * CC]);
    d_gct[b * CC + c] = m;
}

// K4: q = tanh(gct @ Wq^T + bq)
__global__ void proj_q(const float* __restrict__ w, const float* __restrict__ bq) {
    int b = blockIdx.x;
    int o = threadIdx.x;
    float s = bq[o];
    const float* gp = d_gct + b * CC;
    const float* wp = w + o * CC;
    for (int c = 0; c < CC; c++) s += gp[c] * wp[c];
    d_q[b * CC + o] = tanhf(s);
}

// ============================================================
// K5: per (b, chunk of 63 t): gate = sigmoid(h . q), partial
//     max over t of h*gate per channel. Warp per timestep.
// ============================================================
__global__ __launch_bounds__(256) void gate_max() {
    int b  = blockIdx.y;
    int ch = blockIdx.x;
    int tid = threadIdx.x;
    int w = tid >> 5, lane = tid & 31;

    __shared__ float qs[CC];
    __shared__ float wm[8][CC];
    if (tid < CC) qs[tid] = d_q[b * CC + tid];
    __syncthreads();

    float vmax[4] = {-INFINITY, -INFINITY, -INFINITY, -INFINITY};
    for (int it = 0; it < 8; it++) {
        int local = it * 8 + w;
        if (local < CHUNK) {
            int t = ch * CHUNK + local;
            const float* hp = d_h + ((size_t)(b * TOUT + t)) * CC;
            float hv[4];
            float dot = 0.f;
#pragma unroll
            for (int j = 0; j < 4; j++) {
                hv[j] = hp[lane + 32 * j];
                dot += hv[j] * qs[lane + 32 * j];
            }
#pragma unroll
            for (int off = 16; off; off >>= 1)
                dot += __shfl_xor_sync(0xffffffff, dot, off);
            float gate = 1.f / (1.f + expf(-dot));
#pragma unroll
            for (int j = 0; j < 4; j++)
                vmax[j] = fmaxf(vmax[j], hv[j] * gate);
        }
    }
#pragma unroll
    for (int j = 0; j < 4; j++) wm[w][lane + 32 * j] = vmax[j];
    __syncthreads();
    if (tid < CC) {
        float m = wm[0][tid];
#pragma unroll
        for (int i = 1; i < 8; i++) m = fmaxf(m, wm[i][tid]);
        d_part[((size_t)b * NCHUNK + ch) * CC + tid] = m;
    }
}

// K6: final reduce over chunks -> out (B, C)
__global__ void final_max(float* __restrict__ out) {
    int b = blockIdx.x;
    int c = threadIdx.x;
    float m = -INFINITY;
    for (int i = 0; i < NCHUNK; i++)
        m = fmaxf(m, d_part[((size_t)b * NCHUNK + i) * CC + c]);
    out[b * CC + c] = m;
}

// ============================================================
extern "C" void kernel_launch(void* const* d_in, const int* in_sizes, int n_in,
                              void* d_out, int out_size) {
    const float* x   = (const float*)d_in[0];
    const float* ccw = (const float*)d_in[1];
    const float* ccb = (const float*)d_in[2];
    const float* csw = (const float*)d_in[3];
    const float* csb = (const float*)d_in[4];
    const float* mcw = (const float*)d_in[5];
    const float* mcb = (const float*)d_in[6];
    const float* msw = (const float*)d_in[7];
    const float* msb = (const float*)d_in[8];
    const float* gpw = (const float*)d_in[9];
    const float* gpb = (const float*)d_in[10];
    float* out = (float*)d_out;

    prep_wmat<<<(KDIM * NCOLS + 255) / 256, 256>>>(ccw, mcw);
    prep_wst<<<(CC * CC + 255) / 256, 256>>>(csw, msw);

    dim3 g1(NCOLS / BN, (MROWS + BM - 1) / BM);  // (4, 123)
    gemm_conv<<<g1, 256>>>(x);

    glu_share<<<(MROWS + R2 - 1) / R2, 256>>>(ccb, csb, mcb, msb);
    reduce_gct<<<BB, CC>>>();
    proj_q<<<BB, CC>>>(gpw, gpb);
    gate_max<<<dim3(NCHUNK, BB), 256>>>();
    final_max<<<BB, CC>>>(out);
}

// round 4
// speedup vs baseline: 1.0074x; 1.0074x over previous
#include <cuda_runtime.h>
#include <math.h>

// Problem constants
#define BB    4
#define TT    1000000
#define EE    8
#define CC    128
#define KW    512
#define TOUT  1953                 // (1e6 - 512)/512 + 1
#define MROWS (BB * TOUT)          // 7812
#define NCOLS 512                  // 2 branches * 2C? No: ctx 256 + main 256
#define KDIM  4096                 // E * KW

#define NCHUNK 31
#define CHUNK  63                  // 31*63 = 1953

// ---- scratch (static __device__, no allocation) ----
__device__ float d_Wmat[KDIM * NCOLS];      // 8 MB  (kk-major, [kk][n])
__device__ float d_WsT[2][CC * CC];         // share weights transposed [c][o]
__device__ float d_Y[MROWS * NCOLS];        // 16 MB conv outputs (pre-bias)
__device__ float d_g[MROWS * CC];           // ctx branch activations
__device__ float d_h[MROWS * CC];           // main branch activations
__device__ float d_gct[BB * CC];
__device__ float d_q[BB * CC];
__device__ float d_part[BB * NCHUNK * CC];

// ============================================================
// K0a: build Wmat[kk][n]  (kk = k*8 + e), n<256 ctx, n>=256 main
// ============================================================
__global__ void prep_wmat(const float* __restrict__ cw, const float* __restrict__ mw) {
    int idx = blockIdx.x * 256 + threadIdx.x;
    if (idx >= KDIM * NCOLS) return;
    int n  = idx % NCOLS;
    int kk = idx / NCOLS;
    int e = kk & 7;
    int k = kk >> 3;
    float v;
    if (n < 256) v = cw[n * KDIM + e * KW + k];
    else         v = mw[(n - 256) * KDIM + e * KW + k];
    d_Wmat[(size_t)kk * NCOLS + n] = v;
}

// K0b: transpose the two 1x1 share weights: WsT[c][o] = Ws[o][c]
__global__ void prep_wst(const float* __restrict__ cs, const float* __restrict__ ms) {
    int idx = blockIdx.x * 256 + threadIdx.x;
    if (idx >= CC * CC) return;
    int o = idx / CC, c = idx % CC;
    d_WsT[0][c * CC + o] = cs[o * CC + c];
    d_WsT[1][c * CC + o] = ms[o * CC + c];
}

// ============================================================
// K1: SGEMM  Y[7812,512] = A[7812,4096] * Wmat[4096,512]
//     A row r = contiguous window of x (non-overlapping stride==K).
//     BM=64 BN=128 BK=16, 256 threads, 4x8 micro-tile, double-buffered smem.
// ============================================================
#define BM 64
#define BN 128
#define BK 16
#define ASTRIDE 68   // padded, multiple of 4 for float4 smem reads

__global__ __launch_bounds__(256) void gemm_conv(const float* __restrict__ x) {
    __shared__ __align__(16) float As[2][BK * ASTRIDE];
    __shared__ __align__(16) float Bs[2][BK * BN];

    int tid = threadIdx.x;
    int bm = blockIdx.y, bn = blockIdx.x;

    // A-load mapping: one float4 per thread: row am (0..63), k offset ak
    int am = tid >> 2;
    int ak = (tid & 3) * 4;
    int gr = bm * BM + am;
    const float* aptr;
    if (gr < MROWS) {
        int b = gr / TOUT, t = gr % TOUT;
        aptr = x + (size_t)b * TT * EE + (size_t)t * KDIM;
    } else {
        aptr = x;  // harmless garbage; stores guarded
    }

    // B-load mapping: two float4 per thread
    int brow = tid >> 5;          // 0..7 -> rows brow, brow+8
    int bc   = (tid & 31) * 4;    // 0..124
    const float* bbase = d_Wmat + (size_t)bn * BN + bc;

    int tx = tid & 15;            // col group: 8 cols
    int ty = tid >> 4;            // row group: 4 rows

    float acc[4][8];
#pragma unroll
    for (int i = 0; i < 4; i++)
#pragma unroll
        for (int j = 0; j < 8; j++) acc[i][j] = 0.f;

    // prologue: tile 0
    float4 ra = *(const float4*)(aptr + ak);
    float4 rb0 = *(const float4*)(bbase + (size_t)brow * NCOLS);
    float4 rb1 = *(const float4*)(bbase + (size_t)(brow + 8) * NCOLS);

    As[0][(ak + 0) * ASTRIDE + am] = ra.x;
    As[0][(ak + 1) * ASTRIDE + am] = ra.y;
    As[0][(ak + 2) * ASTRIDE + am] = ra.z;
    As[0][(ak + 3) * ASTRIDE + am] = ra.w;
    *(float4*)(&Bs[0][brow * BN + bc])       = rb0;
    *(float4*)(&Bs[0][(brow + 8) * BN + bc]) = rb1;
    __syncthreads();

    const int NK = KDIM / BK;  // 256
    for (int kt = 0; kt < NK; kt++) {
        int cur = kt & 1;
        if (kt + 1 < NK) {
            int k0 = (kt + 1) * BK;
            ra  = *(const float4*)(aptr + k0 + ak);
            rb0 = *(const float4*)(bbase + (size_t)(k0 + brow) * NCOLS);
            rb1 = *(const float4*)(bbase + (size_t)(k0 + brow + 8) * NCOLS);
        }
        const float* Ac = As[cur];
        const float* Bc = Bs[cur];
#pragma unroll
        for (int k = 0; k < BK; k++) {
            float4 av = *(const float4*)(Ac + k * ASTRIDE + ty * 4);
            float4 b0 = *(const float4*)(Bc + k * BN + tx * 8);
            float4 b1 = *(const float4*)(Bc + k * BN + tx * 8 + 4);
            float a_[4] = {av.x, av.y, av.z, av.w};
            float b_[8] = {b0.x, b0.y, b0.z, b0.w, b1.x, b1.y, b1.z, b1.w};
#pragma unroll
            for (int i = 0; i < 4; i++)
#pragma unroll
                for (int j = 0; j < 8; j++)
                    acc[i][j] += a_[i] * b_[j];
        }
        if (kt + 1 < NK) {
            int nxt = cur ^ 1;
            As[nxt][(ak + 0) * ASTRIDE + am] = ra.x;
            As[nxt][(ak + 1) * ASTRIDE + am] = ra.y;
            As[nxt][(ak + 2) * ASTRIDE + am] = ra.z;
            As[nxt][(ak + 3) * ASTRIDE + am] = ra.w;
            *(float4*)(&Bs[nxt][brow * BN + bc])       = rb0;
            *(float4*)(&Bs[nxt][(brow + 8) * BN + bc]) = rb1;
            __syncthreads();
        }
    }

    // epilogue
#pragma unroll
    for (int i = 0; i < 4; i++) {
        int row = bm * BM + ty * 4 + i;
        if (row < MROWS) {
            float* yp = d_Y + (size_t)row * NCOLS + bn * BN + tx * 8;
            float4 w0 = make_float4(acc[i][0], acc[i][1], acc[i][2], acc[i][3]);
            float4 w1 = make_float4(acc[i][4], acc[i][5], acc[i][6], acc[i][7]);
            *(float4*)(yp)     = w0;
            *(float4*)(yp + 4) = w1;
        }
    }
}

// ============================================================
// K2: per-row: bias + GLU -> u (128 per branch), then 1x1 share
//     conv (128x128) + bias + leaky, write d_g / d_h.
//     Block = 32 rows; thread o in [0,256): branch = o>>7.
// ============================================================
#define R2 32
__global__ __launch_bounds__(256) void glu_share(const float* __restrict__ cb,
                                                 const float* __restrict__ csb,
                                                 const float* __restrict__ mb,
                                                 const float* __restrict__ msb) {
    __shared__ float u[R2][256];
    int tid = threadIdx.x;
    int row0 = blockIdx.x * R2;

    for (int idx = tid; idx < R2 * 256; idx += 256) {
        int r = idx >> 8;
        int j = idx & 255;
        int row = row0 + r;
        float val = 0.f;
        if (row < MROWS) {
            const float* yrow = d_Y + (size_t)row * NCOLS;
            int half = j & 127;
            float a, bg;
            if (j < 128) {
                a  = yrow[half]       + cb[half];
                bg = yrow[half + 128] + cb[half + 128];
            } else {
                a  = yrow[half + 256] + mb[half];
                bg = yrow[half + 384] + mb[half + 128];
            }
            val = a / (1.f + expf(-bg));   // a * sigmoid(bg)
        }
        u[r][j] = val;
    }
    __syncthreads();

    int branch = tid >> 7;     // 0 = ctx, 1 = main
    int oc = tid & 127;
    const float* wt = d_WsT[branch];
    int uoff = branch * 128;

    float acc[R2];
#pragma unroll
    for (int r = 0; r < R2; r++) acc[r] = 0.f;

    for (int c = 0; c < CC; c++) {
        float wv = __ldg(&wt[c * CC + oc]);
#pragma unroll
        for (int r = 0; r < R2; r++) acc[r] += wv * u[r][uoff + c];
    }

    float bias = branch ? msb[oc] : csb[oc];
    float* dst = branch ? d_h : d_g;
#pragma unroll
    for (int r = 0; r < R2; r++) {
        int row = row0 + r;
        if (row < MROWS) {
            float v = acc[r] + bias;
            v = (v >= 0.f) ? v : 0.01f * v;
            dst[(size_t)row * CC + oc] = v;
        }
    }
}

// K3: gct[b][c] = max_t g[b,c,t]
__global__ void reduce_gct() {
    int b = blockIdx.x;
    int c = threadIdx.x;
    float m = -INFINITY;
    const float* gp = d_g + (size_t)b * TOUT * CC + c;
    for (int t = 0; t < TOUT; t++) m = fmaxf(m, gp[(size_t)t * CC]);
    d_gct[b * CC + c] = m;
}

// K4: q = tanh(gct @ Wq^T + bq)
__global__ void proj_q(const float* __restrict__ w, const float* __restrict__ bq) {
    int b = blockIdx.x;
    int o = threadIdx.x;
    float s = bq[o];
    const float* gp = d_gct + b * CC;
    const float* wp = w + o * CC;
    for (int c = 0; c < CC; c++) s += gp[c] * wp[c];
    d_q[b * CC + o] = tanhf(s);
}

// ============================================================
// K5: per (b, chunk of 63 t): gate = sigmoid(h . q), partial
//     max over t of h*gate per channel. Warp per timestep.
// ============================================================
__global__ __launch_bounds__(256) void gate_max() {
    int b  = blockIdx.y;
    int ch = blockIdx.x;
    int tid = threadIdx.x;
    int w = tid >> 5, lane = tid & 31;

    __shared__ float qs[CC];
    __shared__ float wm[8][CC];
    if (tid < CC) qs[tid] = d_q[b * CC + tid];
    __syncthreads();

    float vmax[4] = {-INFINITY, -INFINITY, -INFINITY, -INFINITY};
    for (int it = 0; it < 8; it++) {
        int local = it * 8 + w;
        if (local < CHUNK) {
            int t = ch * CHUNK + local;
            const float* hp = d_h + ((size_t)(b * TOUT + t)) * CC;
            float hv[4];
            float dot = 0.f;
#pragma unroll
            for (int j = 0; j < 4; j++) {
                hv[j] = hp[lane + 32 * j];
                dot += hv[j] * qs[lane + 32 * j];
            }
#pragma unroll
            for (int off = 16; off; off >>= 1)
                dot += __shfl_xor_sync(0xffffffff, dot, off);
            float gate = 1.f / (1.f + expf(-dot));
#pragma unroll
            for (int j = 0; j < 4; j++)
                vmax[j] = fmaxf(vmax[j], hv[j] * gate);
        }
    }
#pragma unroll
    for (int j = 0; j < 4; j++) wm[w][lane + 32 * j] = vmax[j];
    __syncthreads();
    if (tid < CC) {
        float m = wm[0][tid];
#pragma unroll
        for (int i = 1; i < 8; i++) m = fmaxf(m, wm[i][tid]);
        d_part[((size_t)b * NCHUNK + ch) * CC + tid] = m;
    }
}

// K6: final reduce over chunks -> out (B, C)
__global__ void final_max(float* __restrict__ out) {
    int b = blockIdx.x;
    int c = threadIdx.x;
    float m = -INFINITY;
    for (int i = 0; i < NCHUNK; i++)
        m = fmaxf(m, d_part[((size_t)b * NCHUNK + i) * CC + c]);
    out[b * CC + c] = m;
}

// ============================================================
extern "C" void kernel_launch(void* const* d_in, const int* in_sizes, int n_in,
                              void* d_out, int out_size) {
    const float* x   = (const float*)d_in[0];
    const float* ccw = (const float*)d_in[1];
    const float* ccb = (const float*)d_in[2];
    const float* csw = (const float*)d_in[3];
    const float* csb = (const float*)d_in[4];
    const float* mcw = (const float*)d_in[5];
    const float* mcb = (const float*)d_in[6];
    const float* msw = (const float*)d_in[7];
    const float* msb = (const float*)d_in[8];
    const float* gpw = (const float*)d_in[9];
    const float* gpb = (const float*)d_in[10];
    float* out = (float*)d_out;

    prep_wmat<<<(KDIM * NCOLS + 255) / 256, 256>>>(ccw, mcw);
    prep_wst<<<(CC * CC + 255) / 256, 256>>>(csw, msw);

    dim3 g1(NCOLS / BN, (MROWS + BM - 1) / BM);  // (4, 123)
    gemm_conv<<<g1, 256>>>(x);

    glu_share<<<(MROWS + R2 - 1) / R2, 256>>>(ccb, csb, mcb, msb);
    reduce_gct<<<BB, CC>>>();
    proj_q<<<BB, CC>>>(gpw, gpb);
    gate_max<<<dim3(NCHUNK, BB), 256>>>();
    final_max<<<BB, CC>>>(out);
}

// round 6
// speedup vs baseline: 3.2239x; 3.2004x over previous
#include <cuda_runtime.h>
#include <cuda_bf16.h>
#include <math.h>
#include <stdint.h>

// ---------------- problem constants ----------------
#define BB    4
#define TT    1000000
#define EE    8
#define CC    128
#define TOUT  1953
#define MROWS (BB * TOUT)          // 7812
#define MP    7936                 // padded M = 62*128
#define NCOLS 512
#define KDIM  4096
#define NCHUNK 31
#define CHUNK  63

// ---------------- GEMM tiling ----------------
#define BM 128
#define BN 128
#define BKC 64                     // K elems per stage
#define NKC (KDIM / BKC)           // 64 chunks
#define STAGE_BYTES 65536          // Ahi16K + Alo16K + Bhi16K + Blo16K
#define NSTAGE 3
#define SMEM_DYN (NSTAGE * STAGE_BYTES)   // 196608

// ---------------- scratch ----------------
__device__ __nv_bfloat16 d_Ahi[(size_t)MP * KDIM];
__device__ __nv_bfloat16 d_Alo[(size_t)MP * KDIM];
__device__ __nv_bfloat16 d_Bhi[(size_t)NCOLS * KDIM];   // column-interleaved (a,gate pairs)
__device__ __nv_bfloat16 d_Blo[(size_t)NCOLS * KDIM];
__device__ float d_U[(size_t)MP * 256];   // GLU out [row][ctx 0..127 | main 0..127]
__device__ float d_WsT[2][CC * CC];
__device__ float d_g[(size_t)MROWS * CC];
__device__ float d_h[(size_t)MROWS * CC];
__device__ float d_gct[BB * CC];
__device__ float d_gpart[BB * NCHUNK * CC];
__device__ float d_q[BB * CC];
__device__ float d_part[BB * NCHUNK * CC];

// ---------------- PTX helpers (sm_80-era only; no tcgen05) ----------------
__device__ __forceinline__ uint32_t smem_u32(const void* p) {
    uint32_t a;
    asm("{ .reg .u64 t; cvta.to.shared.u64 t, %1; cvt.u32.u64 %0, t; }" : "=r"(a) : "l"(p));
    return a;
}
#define CP16(dst, src) asm volatile("cp.async.cg.shared.global [%0], [%1], 16;" :: "r"(dst), "l"(src) : "memory")
#define CP_COMMIT()    asm volatile("cp.async.commit_group;" ::: "memory")
#define CP_WAIT1()     asm volatile("cp.async.wait_group 1;" ::: "memory")

#define LDSM4(r0, r1, r2, r3, addr)                                         \
    asm volatile("ldmatrix.sync.aligned.m8n8.x4.shared.b16 {%0,%1,%2,%3}, [%4];" \
        : "=r"(r0), "=r"(r1), "=r"(r2), "=r"(r3) : "r"(addr))

#define MMA16816(d, a, b)                                                   \
    asm volatile("mma.sync.aligned.m16n8k16.row.col.f32.bf16.bf16.f32 "     \
        "{%0,%1,%2,%3}, {%4,%5,%6,%7}, {%8,%9}, {%0,%1,%2,%3};"             \
        : "+f"((d)[0]), "+f"((d)[1]), "+f"((d)[2]), "+f"((d)[3])            \
        : "r"((a)[0]), "r"((a)[1]), "r"((a)[2]), "r"((a)[3]),               \
          "r"((b)[0]), "r"((b)[1]))

// swizzled byte offset within a 128B-row tile: row r, 16B-column c16
__device__ __forceinline__ uint32_t tile_off(int r, int c16) {
    return (uint32_t)(r * 128 + ((c16 * 16) ^ ((r & 7) << 4)));
}

// ============================================================
// Prep: split x windows into bf16 hi/lo (rows padded to MP)
// ============================================================
__global__ void prep_splitA(const float* __restrict__ x) {
    int r = blockIdx.y;
    int k = blockIdx.x * 1024 + threadIdx.x * 4;
    size_t o = (size_t)r * KDIM + k;
    if (r >= MROWS) {
        *(uint2*)(d_Ahi + o) = make_uint2(0, 0);
        *(uint2*)(d_Alo + o) = make_uint2(0, 0);
        return;
    }
    int b = r / TOUT, t = r % TOUT;
    float4 v = *(const float4*)(x + (size_t)b * TT * EE + (size_t)t * KDIM + k);
    __nv_bfloat16 h0 = __float2bfloat16_rn(v.x), h1 = __float2bfloat16_rn(v.y);
    __nv_bfloat16 h2 = __float2bfloat16_rn(v.z), h3 = __float2bfloat16_rn(v.w);
    __nv_bfloat16 l0 = __float2bfloat16_rn(v.x - __bfloat162float(h0));
    __nv_bfloat16 l1 = __float2bfloat16_rn(v.y - __bfloat162float(h1));
    __nv_bfloat16 l2 = __float2bfloat16_rn(v.z - __bfloat162float(h2));
    __nv_bfloat16 l3 = __float2bfloat16_rn(v.w - __bfloat162float(h3));
    __nv_bfloat162* ph = (__nv_bfloat162*)(d_Ahi + o);
    __nv_bfloat162* pl = (__nv_bfloat162*)(d_Alo + o);
    ph[0] = __nv_bfloat162(h0, h1); ph[1] = __nv_bfloat162(h2, h3);
    pl[0] = __nv_bfloat162(l0, l1); pl[1] = __nv_bfloat162(l2, l3);
}

// B with column interleave: n_new = branch*256 + pair*2 + half
// (pair = GLU channel, half 0 = "a", 1 = "gate"); kk = k*8 + e
__global__ void prep_splitB(const float* __restrict__ cw, const float* __restrict__ mw) {
    int idx = blockIdx.x * 256 + threadIdx.x;
    if (idx >= NCOLS * KDIM) return;
    int n = idx >> 12, kk = idx & 4095;
    int branch = n >> 8;
    int within = n & 255;
    int pair = within >> 1, half = within & 1;
    int oc = half * 128 + pair;               // original out-channel within branch
    int e = kk & 7, k = kk >> 3;
    const float* w = branch ? mw : cw;
    float v = w[(size_t)oc * KDIM + e * 512 + k];
    __nv_bfloat16 hi = __float2bfloat16_rn(v);
    d_Bhi[idx] = hi;
    d_Blo[idx] = __float2bfloat16_rn(v - __bfloat162float(hi));
}

__global__ void prep_wst(const float* __restrict__ cs, const float* __restrict__ ms) {
    int idx = blockIdx.x * 256 + threadIdx.x;
    if (idx >= CC * CC) return;
    int o = idx / CC, c = idx % CC;
    d_WsT[0][c * CC + o] = cs[o * CC + c];
    d_WsT[1][c * CC + o] = ms[o * CC + c];
}

// ============================================================
// K1: split-bf16 HMMA GEMM + fused bias/GLU -> d_U
//     grid (4, 62): x = 128-col tile, y = 128-row tile.
//     256 threads = 8 warps, warp tile 64x32, 3-stage cp.async.
// ============================================================
__global__ __launch_bounds__(256, 1) void gemm_tc(const float* __restrict__ ccb,
                                                  const float* __restrict__ mcb) {
    extern __shared__ char smem[];
    uint32_t sbase = smem_u32(smem);
    int tid = threadIdx.x;
    int lane = tid & 31, wid = tid >> 5;
    int wm = wid & 1, wn = wid >> 1;          // 2 x 4 warp grid
    int bn = blockIdx.x, bm = blockIdx.y;
    int m0 = bm * BM, n0 = bn * BN;

    // ---- cp.async per-thread mapping (16 x 16B per stage) ----
    // idx = tid + i*256 : row = idx>>3 (0..127), c16 = idx&7
    // ---- ldmatrix per-thread constants ----
    int l15 = lane & 15, hh = lane >> 4;
    uint32_t cA[4], swA[4], cB[2], swB[2];
#pragma unroll
    for (int mt = 0; mt < 4; mt++) {
        int r = wm * 64 + mt * 16 + l15;
        cA[mt] = (uint32_t)(r * 128);
        swA[mt] = (uint32_t)((r & 7) << 4);
    }
#pragma unroll
    for (int q = 0; q < 2; q++) {
        int r = wn * 32 + q * 16 + l15;
        cB[q] = (uint32_t)(r * 128);
        swB[q] = (uint32_t)((r & 7) << 4);
    }

    float acc[4][4][4];
#pragma unroll
    for (int mt = 0; mt < 4; mt++)
#pragma unroll
        for (int nt = 0; nt < 4; nt++)
#pragma unroll
            for (int i = 0; i < 4; i++) acc[mt][nt][i] = 0.f;

    // ---- prologue: load stages 0,1 (chunks 0,1) ----
#pragma unroll
    for (int s = 0; s < 2; s++) {
        uint32_t stg = sbase + s * STAGE_BYTES;
        size_t koff = (size_t)s * BKC;
#pragma unroll
        for (int i = 0; i < 4; i++) {
            int idx = tid + i * 256;
            int row = idx >> 3, c16 = idx & 7;
            uint32_t dst = tile_off(row, c16);
            size_t ga = (size_t)(m0 + row) * KDIM + koff + c16 * 8;
            size_t gb = (size_t)(n0 + row) * KDIM + koff + c16 * 8;
            CP16(stg + dst,         d_Ahi + ga);
            CP16(stg + 16384 + dst, d_Alo + ga);
            CP16(stg + 32768 + dst, d_Bhi + gb);
            CP16(stg + 49152 + dst, d_Blo + gb);
        }
        CP_COMMIT();
    }

    // ---- main loop ----
    for (int c = 0; c < NKC; c++) {
        CP_WAIT1();
        __syncthreads();

        // issue chunk c+2 into stage (c+2)%3
        if (c + 2 < NKC) {
            uint32_t stg = sbase + ((c + 2) % NSTAGE) * STAGE_BYTES;
            size_t koff = (size_t)(c + 2) * BKC;
#pragma unroll
            for (int i = 0; i < 4; i++) {
                int idx = tid + i * 256;
                int row = idx >> 3, c16 = idx & 7;
                uint32_t dst = tile_off(row, c16);
                size_t ga = (size_t)(m0 + row) * KDIM + koff + c16 * 8;
                size_t gb = (size_t)(n0 + row) * KDIM + koff + c16 * 8;
                CP16(stg + dst,         d_Ahi + ga);
                CP16(stg + 16384 + dst, d_Alo + ga);
                CP16(stg + 32768 + dst, d_Bhi + gb);
                CP16(stg + 49152 + dst, d_Blo + gb);
            }
        }
        CP_COMMIT();

        uint32_t stA = sbase + (c % NSTAGE) * STAGE_BYTES;
        uint32_t stB = stA + 32768;

#pragma unroll
        for (int kk = 0; kk < 4; kk++) {
            uint32_t ko = (uint32_t)(kk * 32 + hh * 16);
            uint32_t ah[4][4], al[4][4], bh[4][2], bl[4][2];
#pragma unroll
            for (int mt = 0; mt < 4; mt++) {
                uint32_t ad = stA + cA[mt] + (ko ^ swA[mt]);
                LDSM4(ah[mt][0], ah[mt][1], ah[mt][2], ah[mt][3], ad);
                LDSM4(al[mt][0], al[mt][1], al[mt][2], al[mt][3], ad + 16384);
            }
#pragma unroll
            for (int q = 0; q < 2; q++) {
                uint32_t ad = stB + cB[q] + (ko ^ swB[q]);
                uint32_t r0, r1, r2, r3;
                LDSM4(r0, r1, r2, r3, ad);
                bh[2 * q][0] = r0; bh[2 * q + 1][0] = r1;
                bh[2 * q][1] = r2; bh[2 * q + 1][1] = r3;
                LDSM4(r0, r1, r2, r3, ad + 16384);
                bl[2 * q][0] = r0; bl[2 * q + 1][0] = r1;
                bl[2 * q][1] = r2; bl[2 * q + 1][1] = r3;
            }
            // 3 passes: hi*hi, hi*lo, lo*hi
#pragma unroll
            for (int mt = 0; mt < 4; mt++)
#pragma unroll
                for (int nt = 0; nt < 4; nt++)
                    MMA16816(acc[mt][nt], ah[mt], bh[nt]);
#pragma unroll
            for (int mt = 0; mt < 4; mt++)
#pragma unroll
                for (int nt = 0; nt < 4; nt++)
                    MMA16816(acc[mt][nt], ah[mt], bl[nt]);
#pragma unroll
            for (int mt = 0; mt < 4; mt++)
#pragma unroll
                for (int nt = 0; nt < 4; nt++)
                    MMA16816(acc[mt][nt], al[mt], bh[nt]);
        }
    }

    // ---- epilogue: bias + GLU -> d_U ----
    // col(2t) = "a", col(2t+1) = "gate" of pair p (interleaved B layout)
    int g = lane >> 2, t = lane & 3;
    const float* bias = (bn >= 2) ? mcb : ccb;
    int pb = ((bn & 1) << 6) + (wn << 4);     // pair base within branch
    int ucb = ((bn >> 1) << 7);               // d_U column base (branch)
#pragma unroll
    for (int mt = 0; mt < 4; mt++) {
        int r0 = m0 + wm * 64 + mt * 16 + g;
#pragma unroll
        for (int nt = 0; nt < 4; nt++) {
            int p = pb + nt * 4 + t;
            float ba = __ldg(bias + p);
            float bg = __ldg(bias + 128 + p);
            int uc = ucb + p;
            float a0 = acc[mt][nt][0] + ba;
            float g0 = acc[mt][nt][1] + bg;
            d_U[(size_t)r0 * 256 + uc] = a0 / (1.f + __expf(-g0));
            float a1 = acc[mt][nt][2] + ba;
            float g1 = acc[mt][nt][3] + bg;
            d_U[(size_t)(r0 + 8) * 256 + uc] = a1 / (1.f + __expf(-g1));
        }
    }
}

// ============================================================
// K2: 1x1 share conv + leaky. 32 rows/block, 256 thr, 4x8 tile.
// ============================================================
#define SA_ROWS 32
__global__ __launch_bounds__(256) void share_act(const float* __restrict__ csb,
                                                 const float* __restrict__ msb) {
    __shared__ float u[SA_ROWS][260];
    int tid = threadIdx.x;
    int row0 = blockIdx.x * SA_ROWS;

    for (int i = tid; i < SA_ROWS * 64; i += 256) {
        int r = i >> 6, q = (i & 63) * 4;
        int row = row0 + r;
        float4 v = make_float4(0.f, 0.f, 0.f, 0.f);
        if (row < MROWS) v = *(const float4*)(d_U + (size_t)row * 256 + q);
        u[r][q] = v.x; u[r][q + 1] = v.y; u[r][q + 2] = v.z; u[r][q + 3] = v.w;
    }
    __syncthreads();

    int ty = tid >> 5;
    int tx = tid & 31;
    int branch = tx >> 4;
    int olocal = (tx & 15) * 8;
    int uoff = branch * 128;
    const float* wt = d_WsT[branch];

    float acc[4][8];
#pragma unroll
    for (int i = 0; i < 4; i++)
#pragma unroll
        for (int j = 0; j < 8; j++) acc[i][j] = 0.f;

    for (int c = 0; c < CC; c++) {
        float4 w0 = __ldg((const float4*)(wt + c * CC + olocal));
        float4 w1 = __ldg((const float4*)(wt + c * CC + olocal + 4));
        float wv[8] = {w0.x, w0.y, w0.z, w0.w, w1.x, w1.y, w1.z, w1.w};
        float uv[4];
#pragma unroll
        for (int i = 0; i < 4; i++) uv[i] = u[ty * 4 + i][uoff + c];
#pragma unroll
        for (int i = 0; i < 4; i++)
#pragma unroll
            for (int j = 0; j < 8; j++) acc[i][j] += uv[i] * wv[j];
    }

    const float* bs = branch ? msb : csb;
    float b8[8];
#pragma unroll
    for (int j = 0; j < 8; j++) b8[j] = __ldg(bs + olocal + j);
    float* dst = branch ? d_h : d_g;
#pragma unroll
    for (int i = 0; i < 4; i++) {
        int row = row0 + ty * 4 + i;
        if (row < MROWS) {
            float o[8];
#pragma unroll
            for (int j = 0; j < 8; j++) {
                float v = acc[i][j] + b8[j];
                o[j] = (v >= 0.f) ? v : 0.01f * v;
            }
            float* p = dst + (size_t)row * CC + olocal;
            *(float4*)(p)     = make_float4(o[0], o[1], o[2], o[3]);
            *(float4*)(p + 4) = make_float4(o[4], o[5], o[6], o[7]);
        }
    }
}

// K3: gct partial max + final
__global__ void gct_part() {
    int b = blockIdx.y, ch = blockIdx.x, c = threadIdx.x;
    float m = -INFINITY;
    int t1 = min((ch + 1) * CHUNK, TOUT);
    for (int t = ch * CHUNK; t < t1; t++)
        m = fmaxf(m, d_g[((size_t)b * TOUT + t) * CC + c]);
    d_gpart[((size_t)b * NCHUNK + ch) * CC + c] = m;
}
__global__ void gct_final() {
    int b = blockIdx.x, c = threadIdx.x;
    float m = -INFINITY;
    for (int i = 0; i < NCHUNK; i++)
        m = fmaxf(m, d_gpart[((size_t)b * NCHUNK + i) * CC + c]);
    d_gct[b * CC + c] = m;
}

// K4: q = tanh(gct @ Wq^T + bq)
__global__ void proj_q(const float* __restrict__ w, const float* __restrict__ bq) {
    int b = blockIdx.x, o = threadIdx.x;
    float s = bq[o];
    const float* gp = d_gct + b * CC;
    const float* wp = w + o * CC;
    for (int c = 0; c < CC; c++) s += gp[c] * wp[c];
    d_q[b * CC + o] = tanhf(s);
}

// K5: gate = sigmoid(h . q); partial max of h*gate per channel
__global__ __launch_bounds__(256) void gate_max() {
    int b = blockIdx.y, ch = blockIdx.x;
    int tid = threadIdx.x;
    int w = tid >> 5, lane = tid & 31;

    __shared__ float qs[CC];
    __shared__ float wm[8][CC];
    if (tid < CC) qs[tid] = d_q[b * CC + tid];
    __syncthreads();

    float vmax[4] = {-INFINITY, -INFINITY, -INFINITY, -INFINITY};
    for (int it = 0; it < 8; it++) {
        int local = it * 8 + w;
        if (local < CHUNK) {
            int t = ch * CHUNK + local;
            const float* hp = d_h + ((size_t)(b * TOUT + t)) * CC;
            float hv[4];
            float dot = 0.f;
#pragma unroll
            for (int j = 0; j < 4; j++) {
                hv[j] = hp[lane + 32 * j];
                dot += hv[j] * qs[lane + 32 * j];
            }
#pragma unroll
            for (int off = 16; off; off >>= 1)
                dot += __shfl_xor_sync(0xffffffff, dot, off);
            float gate = 1.f / (1.f + __expf(-dot));
#pragma unroll
            for (int j = 0; j < 4; j++)
                vmax[j] = fmaxf(vmax[j], hv[j] * gate);
        }
    }
#pragma unroll
    for (int j = 0; j < 4; j++) wm[w][lane + 32 * j] = vmax[j];
    __syncthreads();
    if (tid < CC) {
        float m = wm[0][tid];
#pragma unroll
        for (int i = 1; i < 8; i++) m = fmaxf(m, wm[i][tid]);
        d_part[((size_t)b * NCHUNK + ch) * CC + tid] = m;
    }
}

// K6: final reduce -> out (B, C)
__global__ void final_max(float* __restrict__ out) {
    int b = blockIdx.x, c = threadIdx.x;
    float m = -INFINITY;
    for (int i = 0; i < NCHUNK; i++)
        m = fmaxf(m, d_part[((size_t)b * NCHUNK + i) * CC + c]);
    out[b * CC + c] = m;
}

// ============================================================
extern "C" void kernel_launch(void* const* d_in, const int* in_sizes, int n_in,
                              void* d_out, int out_size) {
    const float* x   = (const float*)d_in[0];
    const float* ccw = (const float*)d_in[1];
    const float* ccb = (const float*)d_in[2];
    const float* csw = (const float*)d_in[3];
    const float* csb = (const float*)d_in[4];
    const float* mcw = (const float*)d_in[5];
    const float* mcb = (const float*)d_in[6];
    const float* msw = (const float*)d_in[7];
    const float* msb = (const float*)d_in[8];
    const float* gpw = (const float*)d_in[9];
    const float* gpb = (const float*)d_in[10];
    float* out = (float*)d_out;

    static int smem_set = 0;
    if (!smem_set) {
        cudaFuncSetAttribute(gemm_tc, cudaFuncAttributeMaxDynamicSharedMemorySize, SMEM_DYN);
        smem_set = 1;
    }

    prep_splitA<<<dim3(4, MP), 256>>>(x);
    prep_splitB<<<(NCOLS * KDIM + 255) / 256, 256>>>(ccw, mcw);
    prep_wst<<<(CC * CC + 255) / 256, 256>>>(csw, msw);

    gemm_tc<<<dim3(4, MP / BM), 256, SMEM_DYN>>>(ccb, mcb);

    share_act<<<(MROWS + SA_ROWS - 1) / SA_ROWS, 256>>>(csb, msb);
    gct_part<<<dim3(NCHUNK, BB), CC>>>();
    gct_final<<<BB, CC>>>();
    proj_q<<<BB, CC>>>(gpw, gpb);
    gate_max<<<dim3(NCHUNK, BB), 256>>>();
    final_max<<<BB, CC>>>(out);
}

// round 7
// speedup vs baseline: 3.5532x; 1.1021x over previous
#include <cuda_runtime.h>
#include <cuda_bf16.h>
#include <math.h>
#include <stdint.h>

// ---------------- problem constants ----------------
#define BB    4
#define TT    1000000
#define EE    8
#define CC    128
#define TOUT  1953
#define MROWS (BB * TOUT)          // 7812
#define MP    7936                 // padded M = 62*128
#define NCOLS 512
#define KDIM  4096
#define NCHUNK 31
#define CHUNK  63
#define GCHUNKS 63                 // gct chunks per batch (63*31 = 1953)

// ---------------- GEMM tiling ----------------
#define BM 128
#define BN 128
#define BKC 64                     // K elems per stage
#define NKC (KDIM / BKC)           // 64 chunks
#define STAGE_BYTES 65536          // Ahi16K + Alo16K + Bhi16K + Blo16K
#define NSTAGE 3
#define SMEM_DYN (NSTAGE * STAGE_BYTES)   // 196608

// ---------------- scratch ----------------
__device__ __nv_bfloat16 d_Ahi[(size_t)MP * KDIM];
__device__ __nv_bfloat16 d_Alo[(size_t)MP * KDIM];
__device__ __nv_bfloat16 d_Bhi[(size_t)NCOLS * KDIM];   // column-interleaved (a,gate pairs)
__device__ __nv_bfloat16 d_Blo[(size_t)NCOLS * KDIM];
__device__ float d_U[(size_t)MP * 256];   // GLU out [row][ctx 0..127 | main 0..127]
__device__ float d_WsT[2][CC * CC];
__device__ float d_h[(size_t)MROWS * CC];
__device__ float d_gct[BB * CC];
__device__ float d_gpart[BB * GCHUNKS * CC];
__device__ float d_q[BB * CC];
__device__ float d_part[BB * NCHUNK * CC];

// ---------------- PTX helpers (sm_80-era only; no tcgen05) ----------------
__device__ __forceinline__ uint32_t smem_u32(const void* p) {
    uint32_t a;
    asm("{ .reg .u64 t; cvta.to.shared.u64 t, %1; cvt.u32.u64 %0, t; }" : "=r"(a) : "l"(p));
    return a;
}
#define CP16(dst, src) asm volatile("cp.async.cg.shared.global [%0], [%1], 16;" :: "r"(dst), "l"(src) : "memory")
#define CP_COMMIT()    asm volatile("cp.async.commit_group;" ::: "memory")
#define CP_WAIT1()     asm volatile("cp.async.wait_group 1;" ::: "memory")

#define LDSM4(r0, r1, r2, r3, addr)                                         \
    asm volatile("ldmatrix.sync.aligned.m8n8.x4.shared.b16 {%0,%1,%2,%3}, [%4];" \
        : "=r"(r0), "=r"(r1), "=r"(r2), "=r"(r3) : "r"(addr))

#define MMA16816(d, a, b)                                                   \
    asm volatile("mma.sync.aligned.m16n8k16.row.col.f32.bf16.bf16.f32 "     \
        "{%0,%1,%2,%3}, {%4,%5,%6,%7}, {%8,%9}, {%0,%1,%2,%3};"             \
        : "+f"((d)[0]), "+f"((d)[1]), "+f"((d)[2]), "+f"((d)[3])            \
        : "r"((a)[0]), "r"((a)[1]), "r"((a)[2]), "r"((a)[3]),               \
          "r"((b)[0]), "r"((b)[1]))

// swizzled byte offset within a 128B-row tile: row r, 16B-column c16
__device__ __forceinline__ uint32_t tile_off(int r, int c16) {
    return (uint32_t)(r * 128 + ((c16 * 16) ^ ((r & 7) << 4)));
}

// ============================================================
// Prep: split x windows into bf16 hi/lo (rows padded to MP)
// ============================================================
__global__ void prep_splitA(const float* __restrict__ x) {
    int r = blockIdx.y;
    int k = blockIdx.x * 1024 + threadIdx.x * 4;
    size_t o = (size_t)r * KDIM + k;
    if (r >= MROWS) {
        *(uint2*)(d_Ahi + o) = make_uint2(0, 0);
        *(uint2*)(d_Alo + o) = make_uint2(0, 0);
        return;
    }
    int b = r / TOUT, t = r % TOUT;
    float4 v = *(const float4*)(x + (size_t)b * TT * EE + (size_t)t * KDIM + k);
    __nv_bfloat16 h0 = __float2bfloat16_rn(v.x), h1 = __float2bfloat16_rn(v.y);
    __nv_bfloat16 h2 = __float2bfloat16_rn(v.z), h3 = __float2bfloat16_rn(v.w);
    __nv_bfloat16 l0 = __float2bfloat16_rn(v.x - __bfloat162float(h0));
    __nv_bfloat16 l1 = __float2bfloat16_rn(v.y - __bfloat162float(h1));
    __nv_bfloat16 l2 = __float2bfloat16_rn(v.z - __bfloat162float(h2));
    __nv_bfloat16 l3 = __float2bfloat16_rn(v.w - __bfloat162float(h3));
    __nv_bfloat162* ph = (__nv_bfloat162*)(d_Ahi + o);
    __nv_bfloat162* pl = (__nv_bfloat162*)(d_Alo + o);
    ph[0] = __nv_bfloat162(h0, h1); ph[1] = __nv_bfloat162(h2, h3);
    pl[0] = __nv_bfloat162(l0, l1); pl[1] = __nv_bfloat162(l2, l3);
}

// B with column interleave: n_new = branch*256 + pair*2 + half
// (pair = GLU channel, half 0 = "a", 1 = "gate"); kk = k*8 + e
__global__ void prep_splitB(const float* __restrict__ cw, const float* __restrict__ mw) {
    int idx = blockIdx.x * 256 + threadIdx.x;
    if (idx >= NCOLS * KDIM) return;
    int n = idx >> 12, kk = idx & 4095;
    int branch = n >> 8;
    int within = n & 255;
    int pair = within >> 1, half = within & 1;
    int oc = half * 128 + pair;               // original out-channel within branch
    int e = kk & 7, k = kk >> 3;
    const float* w = branch ? mw : cw;
    float v = w[(size_t)oc * KDIM + e * 512 + k];
    __nv_bfloat16 hi = __float2bfloat16_rn(v);
    d_Bhi[idx] = hi;
    d_Blo[idx] = __float2bfloat16_rn(v - __bfloat162float(hi));
}

__global__ void prep_wst(const float* __restrict__ cs, const float* __restrict__ ms) {
    int idx = blockIdx.x * 256 + threadIdx.x;
    if (idx >= CC * CC) return;
    int o = idx / CC, c = idx % CC;
    d_WsT[0][c * CC + o] = cs[o * CC + c];
    d_WsT[1][c * CC + o] = ms[o * CC + c];
}

// ============================================================
// K1: split-bf16 HMMA GEMM + fused bias/GLU -> d_U
//     grid (4, 62); 512 threads = 16 warps (4m x 4n),
//     warp tile 32x32, 3-stage cp.async pipeline.
// ============================================================
__global__ __launch_bounds__(512, 1) void gemm_tc(const float* __restrict__ ccb,
                                                  const float* __restrict__ mcb) {
    extern __shared__ char smem[];
    uint32_t sbase = smem_u32(smem);
    int tid = threadIdx.x;
    int lane = tid & 31, wid = tid >> 5;
    int wm = wid & 3, wn = wid >> 2;          // 4 x 4 warp grid
    int bn = blockIdx.x, bm = blockIdx.y;
    int m0 = bm * BM, n0 = bn * BN;

    int l15 = lane & 15, hh = lane >> 4;
    uint32_t cA[2], swA[2], cB[2], swB[2];
#pragma unroll
    for (int mt = 0; mt < 2; mt++) {
        int r = wm * 32 + mt * 16 + l15;
        cA[mt] = (uint32_t)(r * 128);
        swA[mt] = (uint32_t)((r & 7) << 4);
    }
#pragma unroll
    for (int q = 0; q < 2; q++) {
        int r = wn * 32 + q * 16 + l15;
        cB[q] = (uint32_t)(r * 128);
        swB[q] = (uint32_t)((r & 7) << 4);
    }

    float acc[2][4][4];
#pragma unroll
    for (int mt = 0; mt < 2; mt++)
#pragma unroll
        for (int nt = 0; nt < 4; nt++)
#pragma unroll
            for (int i = 0; i < 4; i++) acc[mt][nt][i] = 0.f;

    // ---- prologue: load stages 0,1 ----
#pragma unroll
    for (int s = 0; s < 2; s++) {
        uint32_t stg = sbase + s * STAGE_BYTES;
        size_t koff = (size_t)s * BKC;
#pragma unroll
        for (int i = 0; i < 2; i++) {
            int idx = tid + i * 512;
            int row = idx >> 3, c16 = idx & 7;
            uint32_t dst = tile_off(row, c16);
            size_t ga = (size_t)(m0 + row) * KDIM + koff + c16 * 8;
            size_t gb = (size_t)(n0 + row) * KDIM + koff + c16 * 8;
            CP16(stg + dst,         d_Ahi + ga);
            CP16(stg + 16384 + dst, d_Alo + ga);
            CP16(stg + 32768 + dst, d_Bhi + gb);
            CP16(stg + 49152 + dst, d_Blo + gb);
        }
        CP_COMMIT();
    }

    // ---- main loop ----
    for (int c = 0; c < NKC; c++) {
        CP_WAIT1();
        __syncthreads();

        if (c + 2 < NKC) {
            uint32_t stg = sbase + ((c + 2) % NSTAGE) * STAGE_BYTES;
            size_t koff = (size_t)(c + 2) * BKC;
#pragma unroll
            for (int i = 0; i < 2; i++) {
                int idx = tid + i * 512;
                int row = idx >> 3, c16 = idx & 7;
                uint32_t dst = tile_off(row, c16);
                size_t ga = (size_t)(m0 + row) * KDIM + koff + c16 * 8;
                size_t gb = (size_t)(n0 + row) * KDIM + koff + c16 * 8;
                CP16(stg + dst,         d_Ahi + ga);
                CP16(stg + 16384 + dst, d_Alo + ga);
                CP16(stg + 32768 + dst, d_Bhi + gb);
                CP16(stg + 49152 + dst, d_Blo + gb);
            }
        }
        CP_COMMIT();

        uint32_t stA = sbase + (c % NSTAGE) * STAGE_BYTES;
        uint32_t stB = stA + 32768;

#pragma unroll
        for (int kk = 0; kk < 4; kk++) {
            uint32_t ko = (uint32_t)(kk * 32 + hh * 16);
            uint32_t ah[2][4], al[2][4], bh[4][2], bl[4][2];
#pragma unroll
            for (int mt = 0; mt < 2; mt++) {
                uint32_t ad = stA + cA[mt] + (ko ^ swA[mt]);
                LDSM4(ah[mt][0], ah[mt][1], ah[mt][2], ah[mt][3], ad);
                LDSM4(al[mt][0], al[mt][1], al[mt][2], al[mt][3], ad + 16384);
            }
#pragma unroll
            for (int q = 0; q < 2; q++) {
                uint32_t ad = stB + cB[q] + (ko ^ swB[q]);
                uint32_t r0, r1, r2, r3;
                LDSM4(r0, r1, r2, r3, ad);
                bh[2 * q][0] = r0; bh[2 * q + 1][0] = r1;
                bh[2 * q][1] = r2; bh[2 * q + 1][1] = r3;
                LDSM4(r0, r1, r2, r3, ad + 16384);
                bl[2 * q][0] = r0; bl[2 * q + 1][0] = r1;
                bl[2 * q][1] = r2; bl[2 * q + 1][1] = r3;
            }
            // 3 passes: hi*hi, hi*lo, lo*hi
#pragma unroll
            for (int mt = 0; mt < 2; mt++)
#pragma unroll
                for (int nt = 0; nt < 4; nt++)
                    MMA16816(acc[mt][nt], ah[mt], bh[nt]);
#pragma unroll
            for (int mt = 0; mt < 2; mt++)
#pragma unroll
                for (int nt = 0; nt < 4; nt++)
                    MMA16816(acc[mt][nt], ah[mt], bl[nt]);
#pragma unroll
            for (int mt = 0; mt < 2; mt++)
#pragma unroll
                for (int nt = 0; nt < 4; nt++)
                    MMA16816(acc[mt][nt], al[mt], bh[nt]);
        }
    }

    // ---- epilogue: bias + GLU -> d_U ----
    // col(2t) = "a", col(2t+1) = "gate" of pair p (interleaved B layout)
    int g = lane >> 2, t = lane & 3;
    const float* bias = (bn >= 2) ? mcb : ccb;
    int ucb = ((bn >> 1) << 7);               // d_U column base (branch)
#pragma unroll
    for (int mt = 0; mt < 2; mt++) {
        int r0 = m0 + wm * 32 + mt * 16 + g;
#pragma unroll
        for (int nt = 0; nt < 4; nt++) {
            int p = ((bn & 1) << 6) + wn * 16 + nt * 4 + t;
            float ba = __ldg(bias + p);
            float bg = __ldg(bias + 128 + p);
            int uc = ucb + p;
            float a0 = acc[mt][nt][0] + ba;
            float g0 = acc[mt][nt][1] + bg;
            d_U[(size_t)r0 * 256 + uc] = a0 / (1.f + __expf(-g0));
            float a1 = acc[mt][nt][2] + ba;
            float g1 = acc[mt][nt][3] + bg;
            d_U[(size_t)(r0 + 8) * 256 + uc] = a1 / (1.f + __expf(-g1));
        }
    }
}

// ============================================================
// K2: 1x1 share conv + leaky. 31 rows/block (63 blocks per batch,
//     never crossing batches). ctx branch: fused per-block channel
//     max (no d_g store). main branch: store d_h.
// ============================================================
#define SA_ROWS 31
__global__ __launch_bounds__(256) void share_act(const float* __restrict__ csb,
                                                 const float* __restrict__ msb) {
    __shared__ float u[32][260];
    __shared__ float redmax[8][CC];
    int tid = threadIdx.x;
    int blk = blockIdx.x;
    int b = blk / GCHUNKS, ch = blk % GCHUNKS;
    int row0 = b * TOUT + ch * SA_ROWS;

    // load 31 valid rows (+1 pad row read from padded d_U; excluded later)
    for (int i = tid; i < 32 * 64; i += 256) {
        int r = i >> 6, q = (i & 63) * 4;
        float4 v = *(const float4*)(d_U + (size_t)(row0 + r) * 256 + q);
        u[r][q] = v.x; u[r][q + 1] = v.y; u[r][q + 2] = v.z; u[r][q + 3] = v.w;
    }
    __syncthreads();

    int ty = tid >> 5;            // 0..7 -> 4 rows each
    int tx = tid & 31;
    int branch = tx >> 4;
    int olocal = (tx & 15) * 8;
    int uoff = branch * 128;
    const float* wt = d_WsT[branch];

    float acc[4][8];
#pragma unroll
    for (int i = 0; i < 4; i++)
#pragma unroll
        for (int j = 0; j < 8; j++) acc[i][j] = 0.f;

    for (int c = 0; c < CC; c++) {
        float4 w0 = __ldg((const float4*)(wt + c * CC + olocal));
        float4 w1 = __ldg((const float4*)(wt + c * CC + olocal + 4));
        float wv[8] = {w0.x, w0.y, w0.z, w0.w, w1.x, w1.y, w1.z, w1.w};
        float uv[4];
#pragma unroll
        for (int i = 0; i < 4; i++) uv[i] = u[ty * 4 + i][uoff + c];
#pragma unroll
        for (int i = 0; i < 4; i++)
#pragma unroll
            for (int j = 0; j < 8; j++) acc[i][j] += uv[i] * wv[j];
    }

    const float* bs = branch ? msb : csb;
    float b8[8];
#pragma unroll
    for (int j = 0; j < 8; j++) b8[j] = __ldg(bs + olocal + j);

    if (branch) {
        // main branch: bias + leaky -> d_h
#pragma unroll
        for (int i = 0; i < 4; i++) {
            int lr = ty * 4 + i;
            if (lr < SA_ROWS) {
                float o[8];
#pragma unroll
                for (int j = 0; j < 8; j++) {
                    float v = acc[i][j] + b8[j];
                    o[j] = (v >= 0.f) ? v : 0.01f * v;
                }
                float* p = d_h + (size_t)(row0 + lr) * CC + olocal;
                *(float4*)(p)     = make_float4(o[0], o[1], o[2], o[3]);
                *(float4*)(p + 4) = make_float4(o[4], o[5], o[6], o[7]);
            }
        }
    } else {
        // ctx branch: bias + leaky -> per-block channel max (no store)
        float m8[8];
#pragma unroll
        for (int j = 0; j < 8; j++) m8[j] = -INFINITY;
#pragma unroll
        for (int i = 0; i < 4; i++) {
            int lr = ty * 4 + i;
            if (lr < SA_ROWS) {
#pragma unroll
                for (int j = 0; j < 8; j++) {
                    float v = acc[i][j] + b8[j];
                    v = (v >= 0.f) ? v : 0.01f * v;
                    m8[j] = fmaxf(m8[j], v);
                }
            }
        }
#pragma unroll
        for (int j = 0; j < 8; j++) redmax[ty][olocal + j] = m8[j];
    }
    __syncthreads();
    if (tid < CC) {
        float m = redmax[0][tid];
#pragma unroll
        for (int i = 1; i < 8; i++) m = fmaxf(m, redmax[i][tid]);
        d_gpart[(size_t)blk * CC + tid] = m;
    }
}

// K3: gct final max over 63 chunks
__global__ void gct_final() {
    int b = blockIdx.x, c = threadIdx.x;
    float m = -INFINITY;
    for (int i = 0; i < GCHUNKS; i++)
        m = fmaxf(m, d_gpart[((size_t)b * GCHUNKS + i) * CC + c]);
    d_gct[b * CC + c] = m;
}

// K4: q = tanh(gct @ Wq^T + bq)
__global__ void proj_q(const float* __restrict__ w, const float* __restrict__ bq) {
    int b = blockIdx.x, o = threadIdx.x;
    float s = bq[o];
    const float* gp = d_gct + b * CC;
    const float* wp = w + o * CC;
    for (int c = 0; c < CC; c++) s += gp[c] * wp[c];
    d_q[b * CC + o] = tanhf(s);
}

// K5: gate = sigmoid(h . q); partial max of h*gate per channel
__global__ __launch_bounds__(256) void gate_max() {
    int b = blockIdx.y, ch = blockIdx.x;
    int tid = threadIdx.x;
    int w = tid >> 5, lane = tid & 31;

    __shared__ float qs[CC];
    __shared__ float wm[8][CC];
    if (tid < CC) qs[tid] = d_q[b * CC + tid];
    __syncthreads();

    float vmax[4] = {-INFINITY, -INFINITY, -INFINITY, -INFINITY};
    for (int it = 0; it < 8; it++) {
        int local = it * 8 + w;
        if (local < CHUNK) {
            int t = ch * CHUNK + local;
            const float* hp = d_h + ((size_t)(b * TOUT + t)) * CC;
            float hv[4];
            float dot = 0.f;
#pragma unroll
            for (int j = 0; j < 4; j++) {
                hv[j] = hp[lane + 32 * j];
                dot += hv[j] * qs[lane + 32 * j];
            }
#pragma unroll
            for (int off = 16; off; off >>= 1)
                dot += __shfl_xor_sync(0xffffffff, dot, off);
            float gate = 1.f / (1.f + __expf(-dot));
#pragma unroll
            for (int j = 0; j < 4; j++)
                vmax[j] = fmaxf(vmax[j], hv[j] * gate);
        }
    }
#pragma unroll
    for (int j = 0; j < 4; j++) wm[w][lane + 32 * j] = vmax[j];
    __syncthreads();
    if (tid < CC) {
        float m = wm[0][tid];
#pragma unroll
        for (int i = 1; i < 8; i++) m = fmaxf(m, wm[i][tid]);
        d_part[((size_t)b * NCHUNK + ch) * CC + tid] = m;
    }
}

// K6: final reduce -> out (B, C)
__global__ void final_max(float* __restrict__ out) {
    int b = blockIdx.x, c = threadIdx.x;
    float m = -INFINITY;
    for (int i = 0; i < NCHUNK; i++)
        m = fmaxf(m, d_part[((size_t)b * NCHUNK + i) * CC + c]);
    out[b * CC + c] = m;
}

// ============================================================
extern "C" void kernel_launch(void* const* d_in, const int* in_sizes, int n_in,
                              void* d_out, int out_size) {
    const float* x   = (const float*)d_in[0];
    const float* ccw = (const float*)d_in[1];
    const float* ccb = (const float*)d_in[2];
    const float* csw = (const float*)d_in[3];
    const float* csb = (const float*)d_in[4];
    const float* mcw = (const float*)d_in[5];
    const float* mcb = (const float*)d_in[6];
    const float* msw = (const float*)d_in[7];
    const float* msb = (const float*)d_in[8];
    const float* gpw = (const float*)d_in[9];
    const float* gpb = (const float*)d_in[10];
    float* out = (float*)d_out;

    static int smem_set = 0;
    if (!smem_set) {
        cudaFuncSetAttribute(gemm_tc, cudaFuncAttributeMaxDynamicSharedMemorySize, SMEM_DYN);
        smem_set = 1;
    }

    prep_splitA<<<dim3(4, MP), 256>>>(x);
    prep_splitB<<<(NCOLS * KDIM + 255) / 256, 256>>>(ccw, mcw);
    prep_wst<<<(CC * CC + 255) / 256, 256>>>(csw, msw);

    gemm_tc<<<dim3(4, MP / BM), 512, SMEM_DYN>>>(ccb, mcb);

    share_act<<<BB * GCHUNKS, 256>>>(csb, msb);
    gct_final<<<BB, CC>>>();
    proj_q<<<BB, CC>>>(gpw, gpb);
    gate_max<<<dim3(NCHUNK, BB), 256>>>();
    final_max<<<BB, CC>>>(out);
}

// round 8
// speedup vs baseline: 7.2586x; 2.0428x over previous
#include <cuda_runtime.h>
#include <cuda_fp16.h>
#include <math.h>
#include <stdint.h>

// ---------------- problem constants ----------------
#define BB    4
#define TT    1000000
#define EE    8
#define CC    128
#define TOUT  1953
#define MROWS (BB * TOUT)          // 7812
#define MP    7936                 // padded M = 62*128
#define NCOLS 512
#define KDIM  4096
#define NCHUNK 31
#define CHUNK  63
#define GCHUNKS 63                 // gct chunks per batch (63*31 = 1953)

// ---------------- GEMM tiling ----------------
#define BM 128
#define BN 128
#define BKC 64                     // K elems per stage
#define NKC (KDIM / BKC)           // 64 chunks
#define STAGE_BYTES 32768          // A 16K + B 16K (fp16)
#define NSTAGE 3
#define SMEM_DYN (NSTAGE * STAGE_BYTES)   // 98304

// ---------------- scratch ----------------
__device__ __half d_Ah[(size_t)MP * KDIM];
__device__ __half d_Bh[(size_t)NCOLS * KDIM];   // column-interleaved (a,gate pairs)
__device__ float d_U[(size_t)MP * 256];   // GLU out [row][ctx 0..127 | main 0..127]
__device__ float d_WsT[2][CC * CC];
__device__ float d_h[(size_t)MROWS * CC];
__device__ float d_gct[BB * CC];
__device__ float d_gpart[BB * GCHUNKS * CC];
__device__ float d_q[BB * CC];
__device__ float d_part[BB * NCHUNK * CC];

// ---------------- PTX helpers ----------------
__device__ __forceinline__ uint32_t smem_u32(const void* p) {
    uint32_t a;
    asm("{ .reg .u64 t; cvta.to.shared.u64 t, %1; cvt.u32.u64 %0, t; }" : "=r"(a) : "l"(p));
    return a;
}
#define CP16(dst, src) asm volatile("cp.async.cg.shared.global [%0], [%1], 16;" :: "r"(dst), "l"(src) : "memory")
#define CP_COMMIT()    asm volatile("cp.async.commit_group;" ::: "memory")
#define CP_WAIT1()     asm volatile("cp.async.wait_group 1;" ::: "memory")

#define LDSM4(r0, r1, r2, r3, addr)                                         \
    asm volatile("ldmatrix.sync.aligned.m8n8.x4.shared.b16 {%0,%1,%2,%3}, [%4];" \
        : "=r"(r0), "=r"(r1), "=r"(r2), "=r"(r3) : "r"(addr))

#define MMA16816(d, a, b)                                                   \
    asm volatile("mma.sync.aligned.m16n8k16.row.col.f32.f16.f16.f32 "       \
        "{%0,%1,%2,%3}, {%4,%5,%6,%7}, {%8,%9}, {%0,%1,%2,%3};"             \
        : "+f"((d)[0]), "+f"((d)[1]), "+f"((d)[2]), "+f"((d)[3])            \
        : "r"((a)[0]), "r"((a)[1]), "r"((a)[2]), "r"((a)[3]),               \
          "r"((b)[0]), "r"((b)[1]))

// swizzled byte offset within a 128B-row tile: row r, 16B-column c16
__device__ __forceinline__ uint32_t tile_off(int r, int c16) {
    return (uint32_t)(r * 128 + ((c16 * 16) ^ ((r & 7) << 4)));
}

// ============================================================
// Prep: convert x windows to fp16 (rows padded to MP)
// 8 elems per thread -> one 16B store
// ============================================================
__global__ void prep_fp16A(const float* __restrict__ x) {
    int r = blockIdx.y;
    int k = blockIdx.x * 2048 + threadIdx.x * 8;
    size_t o = (size_t)r * KDIM + k;
    if (r >= MROWS) {
        *(uint4*)(d_Ah + o) = make_uint4(0, 0, 0, 0);
        return;
    }
    int b = r / TOUT, t = r % TOUT;
    const float* src = x + (size_t)b * TT * EE + (size_t)t * KDIM + k;
    float4 v0 = *(const float4*)(src);
    float4 v1 = *(const float4*)(src + 4);
    __half2* ph = (__half2*)(d_Ah + o);
    ph[0] = __floats2half2_rn(v0.x, v0.y);
    ph[1] = __floats2half2_rn(v0.z, v0.w);
    ph[2] = __floats2half2_rn(v1.x, v1.y);
    ph[3] = __floats2half2_rn(v1.z, v1.w);
}

// B with column interleave: n_new = branch*256 + pair*2 + half
// (pair = GLU channel, half 0 = "a", 1 = "gate"); kk = k*8 + e
__global__ void prep_fp16B(const float* __restrict__ cw, const float* __restrict__ mw) {
    int idx = blockIdx.x * 256 + threadIdx.x;
    if (idx >= NCOLS * KDIM) return;
    int n = idx >> 12, kk = idx & 4095;
    int branch = n >> 8;
    int within = n & 255;
    int pair = within >> 1, half = within & 1;
    int oc = half * 128 + pair;               // original out-channel within branch
    int e = kk & 7, k = kk >> 3;
    const float* w = branch ? mw : cw;
    d_Bh[idx] = __float2half_rn(w[(size_t)oc * KDIM + e * 512 + k]);
}

__global__ void prep_wst(const float* __restrict__ cs, const float* __restrict__ ms) {
    int idx = blockIdx.x * 256 + threadIdx.x;
    if (idx >= CC * CC) return;
    int o = idx / CC, c = idx % CC;
    d_WsT[0][c * CC + o] = cs[o * CC + c];
    d_WsT[1][c * CC + o] = ms[o * CC + c];
}

// ============================================================
// K1: fp16 HMMA GEMM + fused bias/GLU -> d_U
//     grid (4, 62); 256 threads = 8 warps (2m x 4n),
//     warp tile 64x32, 3-stage cp.async, 2 CTAs/SM.
// ============================================================
__global__ __launch_bounds__(256, 2) void gemm_tc(const float* __restrict__ ccb,
                                                  const float* __restrict__ mcb) {
    extern __shared__ char smem[];
    uint32_t sbase = smem_u32(smem);
    int tid = threadIdx.x;
    int lane = tid & 31, wid = tid >> 5;
    int wm = wid & 1, wn = wid >> 1;          // 2 x 4 warp grid
    int bn = blockIdx.x, bm = blockIdx.y;
    int m0 = bm * BM, n0 = bn * BN;

    int l15 = lane & 15, hh = lane >> 4;
    uint32_t cA[4], swA[4], cB[2], swB[2];
#pragma unroll
    for (int mt = 0; mt < 4; mt++) {
        int r = wm * 64 + mt * 16 + l15;
        cA[mt] = (uint32_t)(r * 128);
        swA[mt] = (uint32_t)((r & 7) << 4);
    }
#pragma unroll
    for (int q = 0; q < 2; q++) {
        int r = wn * 32 + q * 16 + l15;
        cB[q] = (uint32_t)(r * 128);
        swB[q] = (uint32_t)((r & 7) << 4);
    }

    float acc[4][4][4];
#pragma unroll
    for (int mt = 0; mt < 4; mt++)
#pragma unroll
        for (int nt = 0; nt < 4; nt++)
#pragma unroll
            for (int i = 0; i < 4; i++) acc[mt][nt][i] = 0.f;

    // ---- prologue: load stages 0,1 ----
#pragma unroll
    for (int s = 0; s < 2; s++) {
        uint32_t stg = sbase + s * STAGE_BYTES;
        size_t koff = (size_t)s * BKC;
#pragma unroll
        for (int i = 0; i < 4; i++) {
            int idx = tid + i * 256;
            int row = idx >> 3, c16 = idx & 7;
            uint32_t dst = tile_off(row, c16);
            size_t ga = (size_t)(m0 + row) * KDIM + koff + c16 * 8;
            size_t gb = (size_t)(n0 + row) * KDIM + koff + c16 * 8;
            CP16(stg + dst,         d_Ah + ga);
            CP16(stg + 16384 + dst, d_Bh + gb);
        }
        CP_COMMIT();
    }

    // ---- main loop ----
    for (int c = 0; c < NKC; c++) {
        CP_WAIT1();
        __syncthreads();

        if (c + 2 < NKC) {
            uint32_t stg = sbase + ((c + 2) % NSTAGE) * STAGE_BYTES;
            size_t koff = (size_t)(c + 2) * BKC;
#pragma unroll
            for (int i = 0; i < 4; i++) {
                int idx = tid + i * 256;
                int row = idx >> 3, c16 = idx & 7;
                uint32_t dst = tile_off(row, c16);
                size_t ga = (size_t)(m0 + row) * KDIM + koff + c16 * 8;
                size_t gb = (size_t)(n0 + row) * KDIM + koff + c16 * 8;
                CP16(stg + dst,         d_Ah + ga);
                CP16(stg + 16384 + dst, d_Bh + gb);
            }
        }
        CP_COMMIT();

        uint32_t stA = sbase + (c % NSTAGE) * STAGE_BYTES;
        uint32_t stB = stA + 16384;

#pragma unroll
        for (int kk = 0; kk < 4; kk++) {
            uint32_t ko = (uint32_t)(kk * 32 + hh * 16);
            uint32_t ah[4][4], bh[4][2];
#pragma unroll
            for (int mt = 0; mt < 4; mt++) {
                uint32_t ad = stA + cA[mt] + (ko ^ swA[mt]);
                LDSM4(ah[mt][0], ah[mt][1], ah[mt][2], ah[mt][3], ad);
            }
#pragma unroll
            for (int q = 0; q < 2; q++) {
                uint32_t ad = stB + cB[q] + (ko ^ swB[q]);
                uint32_t r0, r1, r2, r3;
                LDSM4(r0, r1, r2, r3, ad);
                bh[2 * q][0] = r0; bh[2 * q + 1][0] = r1;
                bh[2 * q][1] = r2; bh[2 * q + 1][1] = r3;
            }
#pragma unroll
            for (int mt = 0; mt < 4; mt++)
#pragma unroll
                for (int nt = 0; nt < 4; nt++)
                    MMA16816(acc[mt][nt], ah[mt], bh[nt]);
        }
    }

    // ---- epilogue: bias + GLU -> d_U ----
    // col(2t) = "a", col(2t+1) = "gate" of pair p (interleaved B layout)
    int g = lane >> 2, t = lane & 3;
    const float* bias = (bn >= 2) ? mcb : ccb;
    int ucb = ((bn >> 1) << 7);               // d_U column base (branch)
#pragma unroll
    for (int mt = 0; mt < 4; mt++) {
        int r0 = m0 + wm * 64 + mt * 16 + g;
#pragma unroll
        for (int nt = 0; nt < 4; nt++) {
            int p = ((bn & 1) << 6) + wn * 16 + nt * 4 + t;
            float ba = __ldg(bias + p);
            float bg = __ldg(bias + 128 + p);
            int uc = ucb + p;
            float a0 = acc[mt][nt][0] + ba;
            float g0 = acc[mt][nt][1] + bg;
            d_U[(size_t)r0 * 256 + uc] = a0 / (1.f + __expf(-g0));
            float a1 = acc[mt][nt][2] + ba;
            float g1 = acc[mt][nt][3] + bg;
            d_U[(size_t)(r0 + 8) * 256 + uc] = a1 / (1.f + __expf(-g1));
        }
    }
}

// ============================================================
// K2: 1x1 share conv + leaky. 31 rows/block (63 blocks per batch,
//     never crossing batches). ctx branch: fused per-block channel
//     max (no d_g store). main branch: store d_h.
// ============================================================
#define SA_ROWS 31
__global__ __launch_bounds__(256) void share_act(const float* __restrict__ csb,
                                                 const float* __restrict__ msb) {
    __shared__ float u[32][260];
    __shared__ float redmax[8][CC];
    int tid = threadIdx.x;
    int blk = blockIdx.x;
    int b = blk / GCHUNKS, ch = blk % GCHUNKS;
    int row0 = b * TOUT + ch * SA_ROWS;

    // load 31 valid rows (+1 pad row; excluded from stores)
    for (int i = tid; i < 32 * 64; i += 256) {
        int r = i >> 6, q = (i & 63) * 4;
        float4 v = *(const float4*)(d_U + (size_t)(row0 + r) * 256 + q);
        u[r][q] = v.x; u[r][q + 1] = v.y; u[r][q + 2] = v.z; u[r][q + 3] = v.w;
    }
    __syncthreads();

    int ty = tid >> 5;            // 0..7 -> 4 rows each
    int tx = tid & 31;
    int branch = tx >> 4;
    int olocal = (tx & 15) * 8;
    int uoff = branch * 128;
    const float* wt = d_WsT[branch];

    float acc[4][8];
#pragma unroll
    for (int i = 0; i < 4; i++)
#pragma unroll
        for (int j = 0; j < 8; j++) acc[i][j] = 0.f;

    for (int c = 0; c < CC; c++) {
        float4 w0 = __ldg((const float4*)(wt + c * CC + olocal));
        float4 w1 = __ldg((const float4*)(wt + c * CC + olocal + 4));
        float wv[8] = {w0.x, w0.y, w0.z, w0.w, w1.x, w1.y, w1.z, w1.w};
        float uv[4];
#pragma unroll
        for (int i = 0; i < 4; i++) uv[i] = u[ty * 4 + i][uoff + c];
#pragma unroll
        for (int i = 0; i < 4; i++)
#pragma unroll
            for (int j = 0; j < 8; j++) acc[i][j] += uv[i] * wv[j];
    }

    const float* bs = branch ? msb : csb;
    float b8[8];
#pragma unroll
    for (int j = 0; j < 8; j++) b8[j] = __ldg(bs + olocal + j);

    if (branch) {
#pragma unroll
        for (int i = 0; i < 4; i++) {
            int lr = ty * 4 + i;
            if (lr < SA_ROWS) {
                float o[8];
#pragma unroll
                for (int j = 0; j < 8; j++) {
                    float v = acc[i][j] + b8[j];
                    o[j] = (v >= 0.f) ? v : 0.01f * v;
                }
                float* p = d_h + (size_t)(row0 + lr) * CC + olocal;
                *(float4*)(p)     = make_float4(o[0], o[1], o[2], o[3]);
                *(float4*)(p + 4) = make_float4(o[4], o[5], o[6], o[7]);
            }
        }
    } else {
        float m8[8];
#pragma unroll
        for (int j = 0; j < 8; j++) m8[j] = -INFINITY;
#pragma unroll
        for (int i = 0; i < 4; i++) {
            int lr = ty * 4 + i;
            if (lr < SA_ROWS) {
#pragma unroll
                for (int j = 0; j < 8; j++) {
                    float v = acc[i][j] + b8[j];
                    v = (v >= 0.f) ? v : 0.01f * v;
                    m8[j] = fmaxf(m8[j], v);
                }
            }
        }
#pragma unroll
        for (int j = 0; j < 8; j++) redmax[ty][olocal + j] = m8[j];
    }
    __syncthreads();
    if (tid < CC) {
        float m = redmax[0][tid];
#pragma unroll
        for (int i = 1; i < 8; i++) m = fmaxf(m, redmax[i][tid]);
        d_gpart[(size_t)blk * CC + tid] = m;
    }
}

// K3: gct final max over 63 chunks
__global__ void gct_final() {
    int b = blockIdx.x, c = threadIdx.x;
    float m = -INFINITY;
    for (int i = 0; i < GCHUNKS; i++)
        m = fmaxf(m, d_gpart[((size_t)b * GCHUNKS + i) * CC + c]);
    d_gct[b * CC + c] = m;
}

// K4: q = tanh(gct @ Wq^T + bq)
__global__ void proj_q(const float* __restrict__ w, const float* __restrict__ bq) {
    int b = blockIdx.x, o = threadIdx.x;
    float s = bq[o];
    const float* gp = d_gct + b * CC;
    const float* wp = w + o * CC;
    for (int c = 0; c < CC; c++) s += gp[c] * wp[c];
    d_q[b * CC + o] = tanhf(s);
}

// K5: gate = sigmoid(h . q); partial max of h*gate per channel
__global__ __launch_bounds__(256) void gate_max() {
    int b = blockIdx.y, ch = blockIdx.x;
    int tid = threadIdx.x;
    int w = tid >> 5, lane = tid & 31;

    __shared__ float qs[CC];
    __shared__ float wm[8][CC];
    if (tid < CC) qs[tid] = d_q[b * CC + tid];
    __syncthreads();

    float vmax[4] = {-INFINITY, -INFINITY, -INFINITY, -INFINITY};
    for (int it = 0; it < 8; it++) {
        int local = it * 8 + w;
        if (local < CHUNK) {
            int t = ch * CHUNK + local;
            const float* hp = d_h + ((size_t)(b * TOUT + t)) * CC;
            float hv[4];
            float dot = 0.f;
#pragma unroll
            for (int j = 0; j < 4; j++) {
                hv[j] = hp[lane + 32 * j];
                dot += hv[j] * qs[lane + 32 * j];
            }
#pragma unroll
            for (int off = 16; off; off >>= 1)
                dot += __shfl_xor_sync(0xffffffff, dot, off);
            float gate = 1.f / (1.f + __expf(-dot));
#pragma unroll
            for (int j = 0; j < 4; j++)
                vmax[j] = fmaxf(vmax[j], hv[j] * gate);
        }
    }
#pragma unroll
    for (int j = 0; j < 4; j++) wm[w][lane + 32 * j] = vmax[j];
    __syncthreads();
    if (tid < CC) {
        float m = wm[0][tid];
#pragma unroll
        for (int i = 1; i < 8; i++) m = fmaxf(m, wm[i][tid]);
        d_part[((size_t)b * NCHUNK + ch) * CC + tid] = m;
    }
}

// K6: final reduce -> out (B, C)
__global__ void final_max(float* __restrict__ out) {
    int b = blockIdx.x, c = threadIdx.x;
    float m = -INFINITY;
    for (int i = 0; i < NCHUNK; i++)
        m = fmaxf(m, d_part[((size_t)b * NCHUNK + i) * CC + c]);
    out[b * CC + c] = m;
}

// ============================================================
extern "C" void kernel_launch(void* const* d_in, const int* in_sizes, int n_in,
                              void* d_out, int out_size) {
    const float* x   = (const float*)d_in[0];
    const float* ccw = (const float*)d_in[1];
    const float* ccb = (const float*)d_in[2];
    const float* csw = (const float*)d_in[3];
    const float* csb = (const float*)d_in[4];
    const float* mcw = (const float*)d_in[5];
    const float* mcb = (const float*)d_in[6];
    const float* msw = (const float*)d_in[7];
    const float* msb = (const float*)d_in[8];
    const float* gpw = (const float*)d_in[9];
    const float* gpb = (const float*)d_in[10];
    float* out = (float*)d_out;

    static int smem_set = 0;
    if (!smem_set) {
        cudaFuncSetAttribute(gemm_tc, cudaFuncAttributeMaxDynamicSharedMemorySize, SMEM_DYN);
        smem_set = 1;
    }

    prep_fp16A<<<dim3(2, MP), 256>>>(x);
    prep_fp16B<<<(NCOLS * KDIM + 255) / 256, 256>>>(ccw, mcw);
    prep_wst<<<(CC * CC + 255) / 256, 256>>>(csw, msw);

    gemm_tc<<<dim3(4, MP / BM), 256, SMEM_DYN>>>(ccb, mcb);

    share_act<<<BB * GCHUNKS, 256>>>(csb, msb);
    gct_final<<<BB, CC>>>();
    proj_q<<<BB, CC>>>(gpw, gpb);
    gate_max<<<dim3(NCHUNK, BB), 256>>>();
    final_max<<<BB, CC>>>(out);
}

// round 10
// speedup vs baseline: 7.3870x; 1.0177x over previous
#include <cuda_runtime.h>
#include <cuda_fp16.h>
#include <math.h>
#include <stdint.h>

// ---------------- problem constants ----------------
#define BB    4
#define TT    1000000
#define EE    8
#define CC    128
#define TOUT  1953
#define MROWS (BB * TOUT)          // 7812
#define MP    7936                 // padded M = 62*128
#define NCOLS 512
#define KDIM  4096
#define NCHUNK 31
#define CHUNK  63
#define GCHUNKS 63                 // gct chunks per batch (63*31 = 1953)

// ---------------- GEMM tiling ----------------
#define BM 128
#define BN 128
#define BKC 64                     // K elems per stage
#define NKC (KDIM / BKC)           // 64 chunks
#define STAGE_BYTES 32768          // A 16K + B 16K (fp16)
#define NSTAGE 3
#define SMEM_DYN (NSTAGE * STAGE_BYTES)   // 98304

// ---------------- scratch ----------------
__device__ __half d_Ah[(size_t)MP * KDIM];
__device__ __half d_Bh[(size_t)NCOLS * KDIM];   // column-interleaved (a,gate pairs)
__device__ float d_U[(size_t)MP * 256];   // GLU out [row][ctx 0..127 | main 0..127]
__device__ float d_WsT[2][CC * CC];
__device__ float d_h[(size_t)MROWS * CC];
__device__ float d_gct[BB * CC];
__device__ float d_gpart[BB * GCHUNKS * CC];
__device__ float d_q[BB * CC];
__device__ float d_part[BB * NCHUNK * CC];

// ---------------- PTX helpers ----------------
__device__ __forceinline__ uint32_t smem_u32(const void* p) {
    uint32_t a;
    asm("{ .reg .u64 t; cvta.to.shared.u64 t, %1; cvt.u32.u64 %0, t; }" : "=r"(a) : "l"(p));
    return a;
}
#define CP16(dst, src) asm volatile("cp.async.cg.shared.global [%0], [%1], 16;" :: "r"(dst), "l"(src) : "memory")
#define CP_COMMIT()    asm volatile("cp.async.commit_group;" ::: "memory")
#define CP_WAIT1()     asm volatile("cp.async.wait_group 1;" ::: "memory")

#define LDSM4(r0, r1, r2, r3, addr)                                         \
    asm volatile("ldmatrix.sync.aligned.m8n8.x4.shared.b16 {%0,%1,%2,%3}, [%4];" \
        : "=r"(r0), "=r"(r1), "=r"(r2), "=r"(r3) : "r"(addr))

#define MMA16816(d, a, b)                                                   \
    asm volatile("mma.sync.aligned.m16n8k16.row.col.f32.f16.f16.f32 "       \
        "{%0,%1,%2,%3}, {%4,%5,%6,%7}, {%8,%9}, {%0,%1,%2,%3};"             \
        : "+f"((d)[0]), "+f"((d)[1]), "+f"((d)[2]), "+f"((d)[3])            \
        : "r"((a)[0]), "r"((a)[1]), "r"((a)[2]), "r"((a)[3]),               \
          "r"((b)[0]), "r"((b)[1]))

// swizzled byte offset within a 128B-row tile: row r, 16B-column c16
__device__ __forceinline__ uint32_t tile_off(int r, int c16) {
    return (uint32_t)(r * 128 + ((c16 * 16) ^ ((r & 7) << 4)));
}

// ============================================================
// Prep: convert x windows to fp16 (rows padded to MP)
// ============================================================
__global__ void prep_fp16A(const float* __restrict__ x) {
    int r = blockIdx.y;
    int k = blockIdx.x * 2048 + threadIdx.x * 8;
    size_t o = (size_t)r * KDIM + k;
    if (r >= MROWS) {
        *(uint4*)(d_Ah + o) = make_uint4(0, 0, 0, 0);
        return;
    }
    int b = r / TOUT, t = r % TOUT;
    const float* src = x + (size_t)b * TT * EE + (size_t)t * KDIM + k;
    float4 v0 = *(const float4*)(src);
    float4 v1 = *(const float4*)(src + 4);
    __half2* ph = (__half2*)(d_Ah + o);
    ph[0] = __floats2half2_rn(v0.x, v0.y);
    ph[1] = __floats2half2_rn(v0.z, v0.w);
    ph[2] = __floats2half2_rn(v1.x, v1.y);
    ph[3] = __floats2half2_rn(v1.z, v1.w);
}

// B with column interleave: n_new = branch*256 + pair*2 + half
// (pair = GLU channel, half 0 = "a", 1 = "gate"); kk = k*8 + e
__global__ void prep_fp16B(const float* __restrict__ cw, const float* __restrict__ mw) {
    int idx = blockIdx.x * 256 + threadIdx.x;
    if (idx >= NCOLS * KDIM) return;
    int n = idx >> 12, kk = idx & 4095;
    int branch = n >> 8;
    int within = n & 255;
    int pair = within >> 1, half = within & 1;
    int oc = half * 128 + pair;               // original out-channel within branch
    int e = kk & 7, k = kk >> 3;
    const float* w = branch ? mw : cw;
    d_Bh[idx] = __float2half_rn(w[(size_t)oc * KDIM + e * 512 + k]);
}

__global__ void prep_wst(const float* __restrict__ cs, const float* __restrict__ ms) {
    int idx = blockIdx.x * 256 + threadIdx.x;
    if (idx >= CC * CC) return;
    int o = idx / CC, c = idx % CC;
    d_WsT[0][c * CC + o] = cs[o * CC + c];
    d_WsT[1][c * CC + o] = ms[o * CC + c];
}

// ============================================================
// K1: fp16 HMMA GEMM + fused bias/GLU -> d_U
//     grid (4, 62); 128 threads = 4 warps (2m x 2n),
//     warp tile 64x64 (cuts smem crossbar traffic 1.5x),
//     3-stage cp.async, 2 CTAs/SM (all 248 CTAs co-resident).
// ============================================================
__global__ __launch_bounds__(128, 2) void gemm_tc(const float* __restrict__ ccb,
                                                  const float* __restrict__ mcb) {
    extern __shared__ char smem[];
    uint32_t sbase = smem_u32(smem);
    int tid = threadIdx.x;
    int lane = tid & 31, wid = tid >> 5;
    int wm = wid & 1, wn = wid >> 1;          // 2 x 2 warp grid
    int bn = blockIdx.x, bm = blockIdx.y;
    int m0 = bm * BM, n0 = bn * BN;

    int l15 = lane & 15, hh = lane >> 4;
    uint32_t cA[4], swA[4], cB[4], swB[4];
#pragma unroll
    for (int mt = 0; mt < 4; mt++) {
        int r = wm * 64 + mt * 16 + l15;
        cA[mt] = (uint32_t)(r * 128);
        swA[mt] = (uint32_t)((r & 7) << 4);
    }
#pragma unroll
    for (int q = 0; q < 4; q++) {
        int r = wn * 64 + q * 16 + l15;
        cB[q] = (uint32_t)(r * 128);
        swB[q] = (uint32_t)((r & 7) << 4);
    }

    float acc[4][8][4];
#pragma unroll
    for (int mt = 0; mt < 4; mt++)
#pragma unroll
        for (int nt = 0; nt < 8; nt++)
#pragma unroll
            for (int i = 0; i < 4; i++) acc[mt][nt][i] = 0.f;

    // ---- prologue: load stages 0,1 (8 A + 8 B cp.async per thread) ----
#pragma unroll
    for (int s = 0; s < 2; s++) {
        uint32_t stg = sbase + s * STAGE_BYTES;
        size_t koff = (size_t)s * BKC;
#pragma unroll
        for (int i = 0; i < 8; i++) {
            int idx = tid + i * 128;
            int row = idx >> 3, c16 = idx & 7;
            uint32_t dst = tile_off(row, c16);
            size_t ga = (size_t)(m0 + row) * KDIM + koff + c16 * 8;
            size_t gb = (size_t)(n0 + row) * KDIM + koff + c16 * 8;
            CP16(stg + dst,         d_Ah + ga);
            CP16(stg + 16384 + dst, d_Bh + gb);
        }
        CP_COMMIT();
    }

    // ---- main loop ----
    for (int c = 0; c < NKC; c++) {
        CP_WAIT1();
        __syncthreads();

        if (c + 2 < NKC) {
            uint32_t stg = sbase + ((c + 2) % NSTAGE) * STAGE_BYTES;
            size_t koff = (size_t)(c + 2) * BKC;
#pragma unroll
            for (int i = 0; i < 8; i++) {
                int idx = tid + i * 128;
                int row = idx >> 3, c16 = idx & 7;
                uint32_t dst = tile_off(row, c16);
                size_t ga = (size_t)(m0 + row) * KDIM + koff + c16 * 8;
                size_t gb = (size_t)(n0 + row) * KDIM + koff + c16 * 8;
                CP16(stg + dst,         d_Ah + ga);
                CP16(stg + 16384 + dst, d_Bh + gb);
            }
        }
        CP_COMMIT();

        uint32_t stA = sbase + (c % NSTAGE) * STAGE_BYTES;
        uint32_t stB = stA + 16384;

#pragma unroll
        for (int kk = 0; kk < 4; kk++) {
            uint32_t ko = (uint32_t)(kk * 32 + hh * 16);
            uint32_t ah[4][4], bh[8][2];
#pragma unroll
            for (int mt = 0; mt < 4; mt++) {
                uint32_t ad = stA + cA[mt] + (ko ^ swA[mt]);
                LDSM4(ah[mt][0], ah[mt][1], ah[mt][2], ah[mt][3], ad);
            }
#pragma unroll
            for (int q = 0; q < 4; q++) {
                uint32_t ad = stB + cB[q] + (ko ^ swB[q]);
                uint32_t r0, r1, r2, r3;
                LDSM4(r0, r1, r2, r3, ad);
                bh[2 * q][0] = r0; bh[2 * q + 1][0] = r1;
                bh[2 * q][1] = r2; bh[2 * q + 1][1] = r3;
            }
#pragma unroll
            for (int mt = 0; mt < 4; mt++)
#pragma unroll
                for (int nt = 0; nt < 8; nt++)
                    MMA16816(acc[mt][nt], ah[mt], bh[nt]);
        }
    }

    // ---- epilogue: bias + GLU -> d_U ----
    // col(2t) = "a", col(2t+1) = "gate" of pair p (interleaved B layout)
    int g = lane >> 2, t = lane & 3;
    const float* bias = (bn >= 2) ? mcb : ccb;
    int ucb = ((bn >> 1) << 7);               // d_U column base (branch)
#pragma unroll
    for (int mt = 0; mt < 4; mt++) {
        int r0 = m0 + wm * 64 + mt * 16 + g;
#pragma unroll
        for (int nt = 0; nt < 8; nt++) {
            int p = ((bn & 1) << 6) + wn * 32 + nt * 4 + t;
            float ba = __ldg(bias + p);
            float bg = __ldg(bias + 128 + p);
            int uc = ucb + p;
            float a0 = acc[mt][nt][0] + ba;
            float g0 = acc[mt][nt][1] + bg;
            d_U[(size_t)r0 * 256 + uc] = a0 / (1.f + __expf(-g0));
            float a1 = acc[mt][nt][2] + ba;
            float g1 = acc[mt][nt][3] + bg;
            d_U[(size_t)(r0 + 8) * 256 + uc] = a1 / (1.f + __expf(-g1));
        }
    }
}

// ============================================================
// K2: 1x1 share conv + leaky. 31 rows/block (63 blocks per batch,
//     never crossing batches). ctx branch: fused per-block channel
//     max (no d_g store). main branch: store d_h.
// ============================================================
#define SA_ROWS 31
__global__ __launch_bounds__(256) void share_act(const float* __restrict__ csb,
                                                 const float* __restrict__ msb) {
    __shared__ float u[32][260];
    __shared__ float redmax[8][CC];
    int tid = threadIdx.x;
    int blk = blockIdx.x;
    int b = blk / GCHUNKS, ch = blk % GCHUNKS;
    int row0 = b * TOUT + ch * SA_ROWS;

    // load 31 valid rows (+1 pad row; excluded from stores)
    for (int i = tid; i < 32 * 64; i += 256) {
        int r = i >> 6, q = (i & 63) * 4;
        float4 v = *(const float4*)(d_U + (size_t)(row0 + r) * 256 + q);
        u[r][q] = v.x; u[r][q + 1] = v.y; u[r][q + 2] = v.z; u[r][q + 3] = v.w;
    }
    __syncthreads();

    int ty = tid >> 5;            // 0..7 -> 4 rows each
    int tx = tid & 31;
    int branch = tx >> 4;
    int olocal = (tx & 15) * 8;
    int uoff = branch * 128;
    const float* wt = d_WsT[branch];

    float acc[4][8];
#pragma unroll
    for (int i = 0; i < 4; i++)
#pragma unroll
        for (int j = 0; j < 8; j++) acc[i][j] = 0.f;

    for (int c = 0; c < CC; c++) {
        float4 w0 = __ldg((const float4*)(wt + c * CC + olocal));
        float4 w1 = __ldg((const float4*)(wt + c * CC + olocal + 4));
        float wv[8] = {w0.x, w0.y, w0.z, w0.w, w1.x, w1.y, w1.z, w1.w};
        float uv[4];
#pragma unroll
        for (int i = 0; i < 4; i++) uv[i] = u[ty * 4 + i][uoff + c];
#pragma unroll
        for (int i = 0; i < 4; i++)
#pragma unroll
            for (int j = 0; j < 8; j++) acc[i][j] += uv[i] * wv[j];
    }

    const float* bs = branch ? msb : csb;
    float b8[8];
#pragma unroll
    for (int j = 0; j < 8; j++) b8[j] = __ldg(bs + olocal + j);

    if (branch) {
#pragma unroll
        for (int i = 0; i < 4; i++) {
            int lr = ty * 4 + i;
            if (lr < SA_ROWS) {
                float o[8];
#pragma unroll
                for (int j = 0; j < 8; j++) {
                    float v = acc[i][j] + b8[j];
                    o[j] = (v >= 0.f) ? v : 0.01f * v;
                }
                float* p = d_h + (size_t)(row0 + lr) * CC + olocal;
                *(float4*)(p)     = make_float4(o[0], o[1], o[2], o[3]);
                *(float4*)(p + 4) = make_float4(o[4], o[5], o[6], o[7]);
            }
        }
    } else {
        float m8[8];
#pragma unroll
        for (int j = 0; j < 8; j++) m8[j] = -INFINITY;
#pragma unroll
        for (int i = 0; i < 4; i++) {
            int lr = ty * 4 + i;
            if (lr < SA_ROWS) {
#pragma unroll
                for (int j = 0; j < 8; j++) {
                    float v = acc[i][j] + b8[j];
                    v = (v >= 0.f) ? v : 0.01f * v;
                    m8[j] = fmaxf(m8[j], v);
                }
            }
        }
#pragma unroll
        for (int j = 0; j < 8; j++) redmax[ty][olocal + j] = m8[j];
    }
    __syncthreads();
    if (tid < CC) {
        float m = redmax[0][tid];
#pragma unroll
        for (int i = 1; i < 8; i++) m = fmaxf(m, redmax[i][tid]);
        d_gpart[(size_t)blk * CC + tid] = m;
    }
}

// K3: gct final max over 63 chunks
__global__ void gct_final() {
    int b = blockIdx.x, c = threadIdx.x;
    float m = -INFINITY;
    for (int i = 0; i < GCHUNKS; i++)
        m = fmaxf(m, d_gpart[((size_t)b * GCHUNKS + i) * CC + c]);
    d_gct[b * CC + c] = m;
}

// K4: q = tanh(gct @ Wq^T + bq)
__global__ void proj_q(const float* __restrict__ w, const float* __restrict__ bq) {
    int b = blockIdx.x, o = threadIdx.x;
    float s = bq[o];
    const float* gp = d_gct + b * CC;
    const float* wp = w + o * CC;
    for (int c = 0; c < CC; c++) s += gp[c] * wp[c];
    d_q[b * CC + o] = tanhf(s);
}

// K5: gate = sigmoid(h . q); partial max of h*gate per channel
__global__ __launch_bounds__(256) void gate_max() {
    int b = blockIdx.y, ch = blockIdx.x;
    int tid = threadIdx.x;
    int w = tid >> 5, lane = tid & 31;

    __shared__ float qs[CC];
    __shared__ float wm[8][CC];
    if (tid < CC) qs[tid] = d_q[b * CC + tid];
    __syncthreads();

    float vmax[4] = {-INFINITY, -INFINITY, -INFINITY, -INFINITY};
    for (int it = 0; it < 8; it++) {
        int local = it * 8 + w;
        if (local < CHUNK) {
            int t = ch * CHUNK + local;
            const float* hp = d_h + ((size_t)(b * TOUT + t)) * CC;
            float hv[4];
            float dot = 0.f;
#pragma unroll
            for (int j = 0; j < 4; j++) {
                hv[j] = hp[lane + 32 * j];
                dot += hv[j] * qs[lane + 32 * j];
            }
#pragma unroll
            for (int off = 16; off; off >>= 1)
                dot += __shfl_xor_sync(0xffffffff, dot, off);
            float gate = 1.f / (1.f + __expf(-dot));
#pragma unroll
            for (int j = 0; j < 4; j++)
                vmax[j] = fmaxf(vmax[j], hv[j] * gate);
        }
    }
#pragma unroll
    for (int j = 0; j < 4; j++) wm[w][lane + 32 * j] = vmax[j];
    __syncthreads();
    if (tid < CC) {
        float m = wm[0][tid];
#pragma unroll
        for (int i = 1; i < 8; i++) m = fmaxf(m, wm[i][tid]);
        d_part[((size_t)b * NCHUNK + ch) * CC + tid] = m;
    }
}

// K6: final reduce -> out (B, C)
__global__ void final_max(float* __restrict__ out) {
    int b = blockIdx.x, c = threadIdx.x;
    float m = -INFINITY;
    for (int i = 0; i < NCHUNK; i++)
        m = fmaxf(m, d_part[((size_t)b * NCHUNK + i) * CC + c]);
    out[b * CC + c] = m;
}

// ============================================================
extern "C" void kernel_launch(void* const* d_in, const int* in_sizes, int n_in,
                              void* d_out, int out_size) {
    const float* x   = (const float*)d_in[0];
    const float* ccw = (const float*)d_in[1];
    const float* ccb = (const float*)d_in[2];
    const float* csw = (const float*)d_in[3];
    const float* csb = (const float*)d_in[4];
    const float* mcw = (const float*)d_in[5];
    const float* mcb = (const float*)d_in[6];
    const float* msw = (const float*)d_in[7];
    const float* msb = (const float*)d_in[8];
    const float* gpw = (const float*)d_in[9];
    const float* gpb = (const float*)d_in[10];
    float* out = (float*)d_out;

    static int smem_set = 0;
    if (!smem_set) {
        cudaFuncSetAttribute(gemm_tc, cudaFuncAttributeMaxDynamicSharedMemorySize, SMEM_DYN);
        smem_set = 1;
    }

    prep_fp16A<<<dim3(2, MP), 256>>>(x);
    prep_fp16B<<<(NCOLS * KDIM + 255) / 256, 256>>>(ccw, mcw);
    prep_wst<<<(CC * CC + 255) / 256, 256>>>(csw, msw);

    gemm_tc<<<dim3(4, MP / BM), 128, SMEM_DYN>>>(ccb, mcb);

    share_act<<<BB * GCHUNKS, 256>>>(csb, msb);
    gct_final<<<BB, CC>>>();
    proj_q<<<BB, CC>>>(gpw, gpb);
    gate_max<<<dim3(NCHUNK, BB), 256>>>();
    final_max<<<BB, CC>>>(out);
}